// round 8
// baseline (speedup 1.0000x reference)
#include <cuda_runtime.h>
#include <cuda_fp16.h>
#include <math.h>
#include <stdint.h>

#define NN 100000
#define NE 1600000
#define ET (NE + NN)
#define LRELU 0.2f

// ---------- scratch ----------
__device__ __half g_h[(size_t)NN * 128];    // fp16 post-GEMM features
__device__ __half g_feat[(size_t)NN * 128]; // fp16 post-LN features
__device__ float g_als[(size_t)NN * 8];
__device__ float g_ald[(size_t)NN * 8];
__device__ __half g_ew[(size_t)ET * 8];     // per-edge softmax weights (8 heads)
__device__ int   g_rowptr[NN + 1];
__device__ int   g_cnt[NN];
__device__ int   g_srcs[ET];
__device__ int   g_dsts[ET];
__device__ int   g_part[128];

// ---------------------- CSR build ----------------------
__global__ void k_init_cnt(int n) {
    int i = blockIdx.x * blockDim.x + threadIdx.x;
    if (i < n) g_cnt[i] = 1;
}
__global__ void k_count(const int* __restrict__ dst, int e) {
    int i = blockIdx.x * blockDim.x + threadIdx.x;
    if (i < e) atomicAdd(&g_cnt[dst[i]], 1);
}
__global__ void k_scan1(int n) {
    __shared__ int sh[1024];
    int tid = threadIdx.x;
    int i = blockIdx.x * 1024 + tid;
    int v = (i < n) ? g_cnt[i] : 0;
    sh[tid] = v;
    __syncthreads();
    #pragma unroll
    for (int o = 1; o < 1024; o <<= 1) {
        int t = (tid >= o) ? sh[tid - o] : 0;
        __syncthreads();
        sh[tid] += t;
        __syncthreads();
    }
    if (i < n) g_rowptr[i] = sh[tid] - v;
    if (tid == 1023) g_part[blockIdx.x] = sh[1023];
}
__global__ void k_scan2(int nb) {
    __shared__ int sh[128];
    int tid = threadIdx.x;
    int v = (tid < nb) ? g_part[tid] : 0;
    sh[tid] = v;
    __syncthreads();
    #pragma unroll
    for (int o = 1; o < 128; o <<= 1) {
        int t = (tid >= o) ? sh[tid - o] : 0;
        __syncthreads();
        sh[tid] += t;
        __syncthreads();
    }
    if (tid < nb) g_part[tid] = sh[tid] - v;
}
__global__ void k_scan3(int n, int etot) {
    int i = blockIdx.x * 1024 + threadIdx.x;
    if (i < n) {
        int p = g_rowptr[i] + g_part[blockIdx.x];
        g_rowptr[i] = p;
        g_srcs[p] = i;
        g_dsts[p] = i;
        g_cnt[i] = p + 1;
    }
    if (i == 0) g_rowptr[n] = etot;
}
__global__ void k_scatter(const int* __restrict__ src, const int* __restrict__ dst, int e) {
    int i = blockIdx.x * blockDim.x + threadIdx.x;
    if (i < e) {
        int d = dst[i];
        int pos = atomicAdd(&g_cnt[d], 1);
        g_srcs[pos] = src[i];
        g_dsts[pos] = d;
    }
}

// ---------------------- edge weight precompute ----------------------
__global__ __launch_bounds__(256) void k_edgew8(const float* __restrict__ als,
                                                const float* __restrict__ ald,
                                                int etot) {
    int i = blockIdx.x * blockDim.x + threadIdx.x;
    if (i >= etot) return;
    int s = g_srcs[i], d = g_dsts[i];
    float4 a0 = *(const float4*)(als + (size_t)s * 8);
    float4 a1 = *(const float4*)(als + (size_t)s * 8 + 4);
    float4 b0 = *(const float4*)(ald + (size_t)d * 8);
    float4 b1 = *(const float4*)(ald + (size_t)d * 8 + 4);
    float x[8] = {a0.x + b0.x, a0.y + b0.y, a0.z + b0.z, a0.w + b0.w,
                  a1.x + b1.x, a1.y + b1.y, a1.z + b1.z, a1.w + b1.w};
    __half hw[8];
    #pragma unroll
    for (int h = 0; h < 8; h++) {
        float v = (x[h] > 0.f) ? x[h] : LRELU * x[h];
        hw[h] = __float2half_rn(__expf(v));
    }
    *(uint4*)(g_ew + (size_t)i * 8) = *(uint4*)hw;
}
__global__ __launch_bounds__(256) void k_edgew1(const float* __restrict__ als,
                                                const float* __restrict__ ald,
                                                int etot) {
    int i = blockIdx.x * blockDim.x + threadIdx.x;
    if (i >= etot) return;
    float x = als[g_srcs[i]] + ald[g_dsts[i]];
    x = (x > 0.f) ? x : LRELU * x;
    g_ew[i] = __float2half_rn(__expf(x));
}

// ---------------------- tf32 helpers ----------------------
__device__ __forceinline__ uint32_t f2tf32(float x) {
    uint32_t r;
    asm("cvt.rna.tf32.f32 %0, %1;" : "=r"(r) : "f"(x));
    return r;
}
#define MMA_TF32(d, a, b) \
    asm volatile("mma.sync.aligned.m16n8k8.row.col.f32.tf32.tf32.f32 " \
        "{%0,%1,%2,%3}, {%4,%5,%6,%7}, {%8,%9}, {%0,%1,%2,%3};" \
        : "+f"((d)[0]), "+f"((d)[1]), "+f"((d)[2]), "+f"((d)[3]) \
        : "r"((a)[0]), "r"((a)[1]), "r"((a)[2]), "r"((a)[3]), \
          "r"((b)[0]), "r"((b)[1]))

template <typename TA>
__device__ __forceinline__ float4 loadA4(const TA* __restrict__ A, size_t elem_off) {
    if constexpr (sizeof(TA) == 4) {
        return *(const float4*)((const float*)A + elem_off);
    } else {
        uint2 u = *(const uint2*)((const __half*)A + elem_off);
        float2 f01 = __half22float2(*(__half2*)&u.x);
        float2 f23 = __half22float2(*(__half2*)&u.y);
        return make_float4(f01.x, f01.y, f23.x, f23.y);
    }
}

// ---------------------- TC GEMM 128x128 + attn coefs (8 heads x 16) ----------------------
template <typename TA>
__global__ __launch_bounds__(256) void k_gemm_attn8_tc(
    const TA* __restrict__ A, const float* __restrict__ W,
    const float* __restrict__ asr, const float* __restrict__ adr,
    __half* __restrict__ H, float* __restrict__ als, float* __restrict__ ald, int n)
{
    __shared__ __align__(16) uint32_t As[128 * 36];
    __shared__ __align__(16) uint32_t Bs[32 * 136];
    int tid = threadIdx.x;
    int wid = tid >> 5, lane = tid & 31;
    int warp_m = wid >> 1, warp_n = wid & 1;
    int g = lane >> 2, c = lane & 3;
    int row0 = blockIdx.x * 128;

    float acc[2][8][4];
    #pragma unroll
    for (int mt = 0; mt < 2; mt++)
        #pragma unroll
        for (int nt = 0; nt < 8; nt++)
            #pragma unroll
            for (int j = 0; j < 4; j++) acc[mt][nt][j] = 0.f;

    for (int k0 = 0; k0 < 128; k0 += 32) {
        #pragma unroll
        for (int l = 0; l < 4; l++) {
            int idx = tid + l * 256;
            int r = idx >> 3, kq = idx & 7;
            int gr = row0 + r;
            float4 v = make_float4(0.f, 0.f, 0.f, 0.f);
            if (gr < n) v = loadA4<TA>(A, (size_t)gr * 128 + k0 + kq * 4);
            uint4 u = {f2tf32(v.x), f2tf32(v.y), f2tf32(v.z), f2tf32(v.w)};
            *(uint4*)&As[r * 36 + kq * 4] = u;
        }
        #pragma unroll
        for (int l = 0; l < 4; l++) {
            int idx = tid + l * 256;
            int kr = idx >> 5, cq = idx & 31;
            float4 v = *(const float4*)(W + (size_t)(k0 + kr) * 128 + cq * 4);
            uint4 u = {f2tf32(v.x), f2tf32(v.y), f2tf32(v.z), f2tf32(v.w)};
            *(uint4*)&Bs[kr * 136 + cq * 4] = u;
        }
        __syncthreads();
        #pragma unroll
        for (int ks = 0; ks < 4; ks++) {
            uint32_t bf[8][2];
            #pragma unroll
            for (int nt = 0; nt < 8; nt++) {
                int col = warp_n * 64 + nt * 8 + g;
                bf[nt][0] = Bs[(ks * 8 + c) * 136 + col];
                bf[nt][1] = Bs[(ks * 8 + c + 4) * 136 + col];
            }
            #pragma unroll
            for (int mt = 0; mt < 2; mt++) {
                int row = warp_m * 32 + mt * 16 + g;
                uint32_t af[4];
                af[0] = As[row * 36 + ks * 8 + c];
                af[1] = As[(row + 8) * 36 + ks * 8 + c];
                af[2] = As[row * 36 + ks * 8 + c + 4];
                af[3] = As[(row + 8) * 36 + ks * 8 + c + 4];
                #pragma unroll
                for (int nt = 0; nt < 8; nt++) MMA_TF32(acc[mt][nt], af, bf[nt]);
            }
        }
        __syncthreads();
    }

    #pragma unroll
    for (int mt = 0; mt < 2; mt++) {
        int r_lo = row0 + warp_m * 32 + mt * 16 + g;
        int r_hi = r_lo + 8;
        float sA0[4] = {0, 0, 0, 0}, sA1[4] = {0, 0, 0, 0};
        float sD0[4] = {0, 0, 0, 0}, sD1[4] = {0, 0, 0, 0};
        #pragma unroll
        for (int nt = 0; nt < 8; nt++) {
            int col = warp_n * 64 + nt * 8 + c * 2;
            int hh = nt >> 1;
            float as0 = asr[col], as1 = asr[col + 1];
            float ad0 = adr[col], ad1 = adr[col + 1];
            float* d = acc[mt][nt];
            sA0[hh] = fmaf(d[0], as0, fmaf(d[1], as1, sA0[hh]));
            sA1[hh] = fmaf(d[2], as0, fmaf(d[3], as1, sA1[hh]));
            sD0[hh] = fmaf(d[0], ad0, fmaf(d[1], ad1, sD0[hh]));
            sD1[hh] = fmaf(d[2], ad0, fmaf(d[3], ad1, sD1[hh]));
            if (r_lo < n) *(__half2*)(H + (size_t)r_lo * 128 + col) = __floats2half2_rn(d[0], d[1]);
            if (r_hi < n) *(__half2*)(H + (size_t)r_hi * 128 + col) = __floats2half2_rn(d[2], d[3]);
        }
        #pragma unroll
        for (int hh = 0; hh < 4; hh++) {
            sA0[hh] += __shfl_xor_sync(0xFFFFFFFFu, sA0[hh], 1);
            sA0[hh] += __shfl_xor_sync(0xFFFFFFFFu, sA0[hh], 2);
            sA1[hh] += __shfl_xor_sync(0xFFFFFFFFu, sA1[hh], 1);
            sA1[hh] += __shfl_xor_sync(0xFFFFFFFFu, sA1[hh], 2);
            sD0[hh] += __shfl_xor_sync(0xFFFFFFFFu, sD0[hh], 1);
            sD0[hh] += __shfl_xor_sync(0xFFFFFFFFu, sD0[hh], 2);
            sD1[hh] += __shfl_xor_sync(0xFFFFFFFFu, sD1[hh], 1);
            sD1[hh] += __shfl_xor_sync(0xFFFFFFFFu, sD1[hh], 2);
        }
        if (c == 0) {
            #pragma unroll
            for (int hh = 0; hh < 4; hh++) {
                int hgl = warp_n * 4 + hh;
                if (r_lo < n) { als[(size_t)r_lo * 8 + hgl] = sA0[hh]; ald[(size_t)r_lo * 8 + hgl] = sD0[hh]; }
                if (r_hi < n) { als[(size_t)r_hi * 8 + hgl] = sA1[hh]; ald[(size_t)r_hi * 8 + hgl] = sD1[hh]; }
            }
        }
    }
}

// ---------------------- TC GEMM 128x64 + attn coefs (1 head x 64) ----------------------
__global__ __launch_bounds__(256) void k_gemm_attn1_tc(
    const __half* __restrict__ A, const float* __restrict__ W,
    const float* __restrict__ asr, const float* __restrict__ adr,
    __half* __restrict__ H, float* __restrict__ als, float* __restrict__ ald, int n)
{
    __shared__ __align__(16) uint32_t As[128 * 36];
    __shared__ __align__(16) uint32_t Bs[32 * 72];
    int tid = threadIdx.x;
    int wid = tid >> 5, lane = tid & 31;
    int g = lane >> 2, c = lane & 3;
    int row0 = blockIdx.x * 128;

    float acc[8][4];
    #pragma unroll
    for (int nt = 0; nt < 8; nt++)
        #pragma unroll
        for (int j = 0; j < 4; j++) acc[nt][j] = 0.f;

    for (int k0 = 0; k0 < 128; k0 += 32) {
        #pragma unroll
        for (int l = 0; l < 4; l++) {
            int idx = tid + l * 256;
            int r = idx >> 3, kq = idx & 7;
            int gr = row0 + r;
            float4 v = make_float4(0.f, 0.f, 0.f, 0.f);
            if (gr < n) v = loadA4<__half>(A, (size_t)gr * 128 + k0 + kq * 4);
            uint4 u = {f2tf32(v.x), f2tf32(v.y), f2tf32(v.z), f2tf32(v.w)};
            *(uint4*)&As[r * 36 + kq * 4] = u;
        }
        #pragma unroll
        for (int l = 0; l < 2; l++) {
            int idx = tid + l * 256;
            int kr = idx >> 4, cq = idx & 15;
            float4 v = *(const float4*)(W + (size_t)(k0 + kr) * 64 + cq * 4);
            uint4 u = {f2tf32(v.x), f2tf32(v.y), f2tf32(v.z), f2tf32(v.w)};
            *(uint4*)&Bs[kr * 72 + cq * 4] = u;
        }
        __syncthreads();
        #pragma unroll
        for (int ks = 0; ks < 4; ks++) {
            int row = wid * 16 + g;
            uint32_t af[4];
            af[0] = As[row * 36 + ks * 8 + c];
            af[1] = As[(row + 8) * 36 + ks * 8 + c];
            af[2] = As[row * 36 + ks * 8 + c + 4];
            af[3] = As[(row + 8) * 36 + ks * 8 + c + 4];
            #pragma unroll
            for (int nt = 0; nt < 8; nt++) {
                int col = nt * 8 + g;
                uint32_t bf[2];
                bf[0] = Bs[(ks * 8 + c) * 72 + col];
                bf[1] = Bs[(ks * 8 + c + 4) * 72 + col];
                MMA_TF32(acc[nt], af, bf);
            }
        }
        __syncthreads();
    }

    int r_lo = row0 + wid * 16 + g;
    int r_hi = r_lo + 8;
    float sA0 = 0.f, sA1 = 0.f, sD0 = 0.f, sD1 = 0.f;
    #pragma unroll
    for (int nt = 0; nt < 8; nt++) {
        int col = nt * 8 + c * 2;
        float as0 = asr[col], as1 = asr[col + 1];
        float ad0 = adr[col], ad1 = adr[col + 1];
        float* d = acc[nt];
        sA0 = fmaf(d[0], as0, fmaf(d[1], as1, sA0));
        sA1 = fmaf(d[2], as0, fmaf(d[3], as1, sA1));
        sD0 = fmaf(d[0], ad0, fmaf(d[1], ad1, sD0));
        sD1 = fmaf(d[2], ad0, fmaf(d[3], ad1, sD1));
        if (r_lo < n) *(__half2*)(H + (size_t)r_lo * 64 + col) = __floats2half2_rn(d[0], d[1]);
        if (r_hi < n) *(__half2*)(H + (size_t)r_hi * 64 + col) = __floats2half2_rn(d[2], d[3]);
    }
    sA0 += __shfl_xor_sync(0xFFFFFFFFu, sA0, 1); sA0 += __shfl_xor_sync(0xFFFFFFFFu, sA0, 2);
    sA1 += __shfl_xor_sync(0xFFFFFFFFu, sA1, 1); sA1 += __shfl_xor_sync(0xFFFFFFFFu, sA1, 2);
    sD0 += __shfl_xor_sync(0xFFFFFFFFu, sD0, 1); sD0 += __shfl_xor_sync(0xFFFFFFFFu, sD0, 2);
    sD1 += __shfl_xor_sync(0xFFFFFFFFu, sD1, 1); sD1 += __shfl_xor_sync(0xFFFFFFFFu, sD1, 2);
    if (c == 0) {
        if (r_lo < n) { als[r_lo] = sA0; ald[r_lo] = sD0; }
        if (r_hi < n) { als[r_hi] = sA1; ald[r_hi] = sD1; }
    }
}

// ---------------------- aggregation (8 heads x 16): 2 edges/step, uint4 gathers ----------------------
__global__ __launch_bounds__(256) void k_agg8(
    const __half* __restrict__ H, const float* __restrict__ bias,
    const float* __restrict__ lng, const float* __restrict__ lnb,
    __half* __restrict__ out, int n)
{
    int w = (blockIdx.x * blockDim.x + threadIdx.x) >> 5;
    if (w >= n) return;
    int lane = threadIdx.x & 31;
    int half16 = lane >> 4;        // which edge of the pair
    int l16 = lane & 15;
    int d0 = l16 * 8;              // this lane covers dims d0..d0+7 (one head: l16>>1)
    int hd = l16 >> 1;
    int s = g_rowptr[w], e2 = g_rowptr[w + 1];

    float acc[8];
    #pragma unroll
    for (int k = 0; k < 8; k++) acc[k] = 0.f;
    float denom = 0.f;

    int i = s;
    for (; i + 4 <= e2; i += 4) {
        int i0 = i + half16, i1 = i + 2 + half16;
        int idx0 = g_srcs[i0], idx1 = g_srcs[i1];
        float w0 = __half2float(g_ew[(size_t)i0 * 8 + hd]);
        float w1 = __half2float(g_ew[(size_t)i1 * 8 + hd]);
        uint4 r0 = *(const uint4*)(H + (size_t)idx0 * 128 + d0);
        uint4 r1 = *(const uint4*)(H + (size_t)idx1 * 128 + d0);
        denom += w0 + w1;
        {
            float2 f0 = __half22float2(*(__half2*)&r0.x);
            float2 f1 = __half22float2(*(__half2*)&r0.y);
            float2 f2 = __half22float2(*(__half2*)&r0.z);
            float2 f3 = __half22float2(*(__half2*)&r0.w);
            acc[0] = fmaf(w0, f0.x, acc[0]); acc[1] = fmaf(w0, f0.y, acc[1]);
            acc[2] = fmaf(w0, f1.x, acc[2]); acc[3] = fmaf(w0, f1.y, acc[3]);
            acc[4] = fmaf(w0, f2.x, acc[4]); acc[5] = fmaf(w0, f2.y, acc[5]);
            acc[6] = fmaf(w0, f3.x, acc[6]); acc[7] = fmaf(w0, f3.y, acc[7]);
        }
        {
            float2 f0 = __half22float2(*(__half2*)&r1.x);
            float2 f1 = __half22float2(*(__half2*)&r1.y);
            float2 f2 = __half22float2(*(__half2*)&r1.z);
            float2 f3 = __half22float2(*(__half2*)&r1.w);
            acc[0] = fmaf(w1, f0.x, acc[0]); acc[1] = fmaf(w1, f0.y, acc[1]);
            acc[2] = fmaf(w1, f1.x, acc[2]); acc[3] = fmaf(w1, f1.y, acc[3]);
            acc[4] = fmaf(w1, f2.x, acc[4]); acc[5] = fmaf(w1, f2.y, acc[5]);
            acc[6] = fmaf(w1, f3.x, acc[6]); acc[7] = fmaf(w1, f3.y, acc[7]);
        }
    }
    for (; i < e2; i += 2) {
        int i0 = i + half16;
        bool valid = i0 < e2;
        int idx0 = valid ? g_srcs[i0] : w;
        float w0 = valid ? __half2float(g_ew[(size_t)i0 * 8 + hd]) : 0.f;
        uint4 r0 = *(const uint4*)(H + (size_t)idx0 * 128 + d0);
        denom += w0;
        float2 f0 = __half22float2(*(__half2*)&r0.x);
        float2 f1 = __half22float2(*(__half2*)&r0.y);
        float2 f2 = __half22float2(*(__half2*)&r0.z);
        float2 f3 = __half22float2(*(__half2*)&r0.w);
        acc[0] = fmaf(w0, f0.x, acc[0]); acc[1] = fmaf(w0, f0.y, acc[1]);
        acc[2] = fmaf(w0, f1.x, acc[2]); acc[3] = fmaf(w0, f1.y, acc[3]);
        acc[4] = fmaf(w0, f2.x, acc[4]); acc[5] = fmaf(w0, f2.y, acc[5]);
        acc[6] = fmaf(w0, f3.x, acc[6]); acc[7] = fmaf(w0, f3.y, acc[7]);
    }

    // merge the two 16-lane halves (same dims at lane ^ 16)
    #pragma unroll
    for (int k = 0; k < 8; k++) acc[k] += __shfl_xor_sync(0xFFFFFFFFu, acc[k], 16);
    denom += __shfl_xor_sync(0xFFFFFFFFu, denom, 16);

    float inv = 1.f / denom;
    float4 b0 = *(const float4*)(bias + d0);
    float4 b1 = *(const float4*)(bias + d0 + 4);
    float o[8];
    o[0] = fmaf(acc[0], inv, b0.x); o[1] = fmaf(acc[1], inv, b0.y);
    o[2] = fmaf(acc[2], inv, b0.z); o[3] = fmaf(acc[3], inv, b0.w);
    o[4] = fmaf(acc[4], inv, b1.x); o[5] = fmaf(acc[5], inv, b1.y);
    o[6] = fmaf(acc[6], inv, b1.z); o[7] = fmaf(acc[7], inv, b1.w);

    // LayerNorm over 128 dims (each dim counted twice across the warp)
    float sm = 0.f;
    #pragma unroll
    for (int k = 0; k < 8; k++) sm += o[k];
    #pragma unroll
    for (int off = 16; off; off >>= 1) sm += __shfl_xor_sync(0xFFFFFFFFu, sm, off);
    float mu = sm * (1.f / 256.f);
    float q = 0.f;
    float d[8];
    #pragma unroll
    for (int k = 0; k < 8; k++) { d[k] = o[k] - mu; q = fmaf(d[k], d[k], q); }
    #pragma unroll
    for (int off = 16; off; off >>= 1) q += __shfl_xor_sync(0xFFFFFFFFu, q, off);
    float rstd = rsqrtf(q * (1.f / 256.f) + 1e-5f);
    float4 g0 = *(const float4*)(lng + d0);
    float4 g1 = *(const float4*)(lng + d0 + 4);
    float4 c0 = *(const float4*)(lnb + d0);
    float4 c1 = *(const float4*)(lnb + d0 + 4);
    float gv[8] = {g0.x, g0.y, g0.z, g0.w, g1.x, g1.y, g1.z, g1.w};
    float cv[8] = {c0.x, c0.y, c0.z, c0.w, c1.x, c1.y, c1.z, c1.w};
    __half hv[8];
    #pragma unroll
    for (int k = 0; k < 8; k++) {
        float v = fmaxf(fmaf(d[k] * rstd, gv[k], cv[k]), 0.f);
        hv[k] = __float2half_rn(v);
    }
    if (half16 == 0) *(uint4*)(out + (size_t)w * 128 + d0) = *(uint4*)hv;
}

// ---------------------- aggregation (1 head x 64) + log_softmax ----------------------
__global__ __launch_bounds__(256) void k_agg1_lsm(
    const __half* __restrict__ H, const float* __restrict__ bias,
    float* __restrict__ out, int n)
{
    int w = (blockIdx.x * blockDim.x + threadIdx.x) >> 5;
    if (w >= n) return;
    int lane = threadIdx.x & 31;
    int s = g_rowptr[w], e2 = g_rowptr[w + 1];
    int d0 = lane * 2;

    float denom = 0.f, acc0 = 0.f, acc1 = 0.f;
    int i = s;
    for (; i + 4 <= e2; i += 4) {
        int sv[4];
        float wv[4];
        #pragma unroll
        for (int j = 0; j < 4; j++) sv[j] = g_srcs[i + j];
        #pragma unroll
        for (int j = 0; j < 4; j++) wv[j] = __half2float(g_ew[i + j]);
        __half2 hv[4];
        #pragma unroll
        for (int j = 0; j < 4; j++) hv[j] = *(const __half2*)(H + (size_t)sv[j] * 64 + d0);
        #pragma unroll
        for (int j = 0; j < 4; j++) {
            denom += wv[j];
            float2 f = __half22float2(hv[j]);
            acc0 = fmaf(wv[j], f.x, acc0);
            acc1 = fmaf(wv[j], f.y, acc1);
        }
    }
    for (; i < e2; ++i) {
        int s0 = g_srcs[i];
        float w0 = __half2float(g_ew[i]);
        denom += w0;
        float2 f = __half22float2(*(const __half2*)(H + (size_t)s0 * 64 + d0));
        acc0 = fmaf(w0, f.x, acc0); acc1 = fmaf(w0, f.y, acc1);
    }
    float inv = 1.f / denom;
    float v0 = fmaf(acc0, inv, bias[d0]);
    float v1 = fmaf(acc1, inv, bias[d0 + 1]);
    float mx = fmaxf(v0, v1);
    #pragma unroll
    for (int o = 16; o; o >>= 1) mx = fmaxf(mx, __shfl_xor_sync(0xFFFFFFFFu, mx, o));
    float se = __expf(v0 - mx) + __expf(v1 - mx);
    #pragma unroll
    for (int o = 16; o; o >>= 1) se += __shfl_xor_sync(0xFFFFFFFFu, se, o);
    float lse = mx + __logf(se);
    out[(size_t)w * 64 + d0] = v0 - lse;
    out[(size_t)w * 64 + d0 + 1] = v1 - lse;
}

// ---------------------- launcher ----------------------
extern "C" void kernel_launch(void* const* d_in, const int* in_sizes, int n_in,
                              void* d_out, int out_size) {
    const float* x   = (const float*)d_in[0];
    const int*   ei  = (const int*)d_in[1];
    const float* W0  = (const float*)d_in[2];
    const float* as0 = (const float*)d_in[3];
    const float* ad0 = (const float*)d_in[4];
    const float* b0  = (const float*)d_in[5];
    const float* W1  = (const float*)d_in[6];
    const float* as1 = (const float*)d_in[7];
    const float* ad1 = (const float*)d_in[8];
    const float* b1  = (const float*)d_in[9];
    const float* W2  = (const float*)d_in[10];
    const float* as2 = (const float*)d_in[11];
    const float* ad2 = (const float*)d_in[12];
    const float* b2  = (const float*)d_in[13];
    const float* ln1g = (const float*)d_in[14];
    const float* ln1b = (const float*)d_in[15];
    const float* ln2g = (const float*)d_in[16];
    const float* ln2b = (const float*)d_in[17];
    float* out = (float*)d_out;

    const int n = in_sizes[0] / 128;
    const int e = in_sizes[1] / 2;
    const int etot = e + n;
    const int* src = ei;
    const int* dst = ei + e;

    __half *h, *feat;
    float *als, *ald;
    cudaGetSymbolAddress((void**)&h, g_h);
    cudaGetSymbolAddress((void**)&feat, g_feat);
    cudaGetSymbolAddress((void**)&als, g_als);
    cudaGetSymbolAddress((void**)&ald, g_ald);

    const int nb_nodes256 = (n + 255) / 256;
    const int nb_edges256 = (e + 255) / 256;
    const int nb_etot256 = (etot + 255) / 256;
    const int nb_scan = (n + 1023) / 1024;
    const int nb_warp = (n * 32 + 255) / 256;
    const int nb_gemm = (n + 127) / 128;

    k_init_cnt<<<nb_nodes256, 256>>>(n);
    k_count<<<nb_edges256, 256>>>(dst, e);
    k_scan1<<<nb_scan, 1024>>>(n);
    k_scan2<<<1, 128>>>(nb_scan);
    k_scan3<<<nb_scan, 1024>>>(n, etot);
    k_scatter<<<nb_edges256, 256>>>(src, dst, e);

    k_gemm_attn8_tc<float><<<nb_gemm, 256>>>(x, W0, as0, ad0, h, als, ald, n);
    k_edgew8<<<nb_etot256, 256>>>(als, ald, etot);
    k_agg8<<<nb_warp, 256>>>(h, b0, ln1g, ln1b, feat, n);

    k_gemm_attn8_tc<__half><<<nb_gemm, 256>>>(feat, W1, as1, ad1, h, als, ald, n);
    k_edgew8<<<nb_etot256, 256>>>(als, ald, etot);
    k_agg8<<<nb_warp, 256>>>(h, b1, ln2g, ln2b, feat, n);

    k_gemm_attn1_tc<<<nb_gemm, 256>>>(feat, W2, as2, ad2, h, als, ald, n);
    k_edgew1<<<nb_etot256, 256>>>(als, ald, etot);
    k_agg1_lsm<<<nb_warp, 256>>>(h, b2, out, n);
}

// round 9
// speedup vs baseline: 1.0630x; 1.0630x over previous
#include <cuda_runtime.h>
#include <cuda_fp16.h>
#include <math.h>
#include <stdint.h>

#define NN 100000
#define NE 1600000
#define ET (NE + NN)
#define LRELU 0.2f

// ---------- scratch ----------
__device__ __half g_h[(size_t)NN * 128];    // fp16 post-GEMM features
__device__ __half g_feat[(size_t)NN * 128]; // fp16 post-LN features
__device__ float g_als[(size_t)NN * 8];
__device__ float g_ald[(size_t)NN * 8];
__device__ __half g_ew[(size_t)ET * 8];     // per-edge softmax weights
__device__ int   g_rowptr[NN + 1];
__device__ int   g_cnt[NN];
__device__ int   g_srcs[ET];
__device__ int   g_dsts[ET];
__device__ int   g_part[128];

// ---------- side stream for CSR/GEMM overlap (created at load, reused) ----------
static cudaStream_t g_sB;
static cudaEvent_t g_evFork, g_evJoin;
namespace {
struct StreamInit {
    StreamInit() {
        cudaStreamCreateWithFlags(&g_sB, cudaStreamNonBlocking);
        cudaEventCreateWithFlags(&g_evFork, cudaEventDisableTiming);
        cudaEventCreateWithFlags(&g_evJoin, cudaEventDisableTiming);
    }
};
StreamInit g_streamInit;
}

// ---------------------- CSR build ----------------------
__global__ void k_init_cnt(int n) {
    int i = blockIdx.x * blockDim.x + threadIdx.x;
    if (i < n) g_cnt[i] = 1;
}
__global__ void k_count(const int* __restrict__ dst, int e) {
    int i = blockIdx.x * blockDim.x + threadIdx.x;
    if (i < e) atomicAdd(&g_cnt[dst[i]], 1);
}
__global__ void k_scan1(int n) {
    __shared__ int sh[1024];
    int tid = threadIdx.x;
    int i = blockIdx.x * 1024 + tid;
    int v = (i < n) ? g_cnt[i] : 0;
    sh[tid] = v;
    __syncthreads();
    #pragma unroll
    for (int o = 1; o < 1024; o <<= 1) {
        int t = (tid >= o) ? sh[tid - o] : 0;
        __syncthreads();
        sh[tid] += t;
        __syncthreads();
    }
    if (i < n) g_rowptr[i] = sh[tid] - v;
    if (tid == 1023) g_part[blockIdx.x] = sh[1023];
}
__global__ void k_scan2(int nb) {
    __shared__ int sh[128];
    int tid = threadIdx.x;
    int v = (tid < nb) ? g_part[tid] : 0;
    sh[tid] = v;
    __syncthreads();
    #pragma unroll
    for (int o = 1; o < 128; o <<= 1) {
        int t = (tid >= o) ? sh[tid - o] : 0;
        __syncthreads();
        sh[tid] += t;
        __syncthreads();
    }
    if (tid < nb) g_part[tid] = sh[tid] - v;
}
__global__ void k_scan3(int n, int etot) {
    int i = blockIdx.x * 1024 + threadIdx.x;
    if (i < n) {
        int p = g_rowptr[i] + g_part[blockIdx.x];
        g_rowptr[i] = p;
        g_srcs[p] = i;
        g_dsts[p] = i;
        g_cnt[i] = p + 1;
    }
    if (i == 0) g_rowptr[n] = etot;
}
__global__ void k_scatter(const int* __restrict__ src, const int* __restrict__ dst, int e) {
    int i = blockIdx.x * blockDim.x + threadIdx.x;
    if (i < e) {
        int d = dst[i];
        int pos = atomicAdd(&g_cnt[d], 1);
        g_srcs[pos] = src[i];
        g_dsts[pos] = d;
    }
}

// ---------------------- edge weight precompute ----------------------
__global__ __launch_bounds__(256) void k_edgew8(const float* __restrict__ als,
                                                const float* __restrict__ ald,
                                                int etot) {
    int i = blockIdx.x * blockDim.x + threadIdx.x;
    if (i >= etot) return;
    int s = g_srcs[i], d = g_dsts[i];
    float4 a0 = *(const float4*)(als + (size_t)s * 8);
    float4 a1 = *(const float4*)(als + (size_t)s * 8 + 4);
    float4 b0 = *(const float4*)(ald + (size_t)d * 8);
    float4 b1 = *(const float4*)(ald + (size_t)d * 8 + 4);
    float x[8] = {a0.x + b0.x, a0.y + b0.y, a0.z + b0.z, a0.w + b0.w,
                  a1.x + b1.x, a1.y + b1.y, a1.z + b1.z, a1.w + b1.w};
    __half hw[8];
    #pragma unroll
    for (int h = 0; h < 8; h++) {
        float v = (x[h] > 0.f) ? x[h] : LRELU * x[h];
        hw[h] = __float2half_rn(__expf(v));
    }
    *(uint4*)(g_ew + (size_t)i * 8) = *(uint4*)hw;
}
__global__ __launch_bounds__(256) void k_edgew1(const float* __restrict__ als,
                                                const float* __restrict__ ald,
                                                int etot) {
    int i = blockIdx.x * blockDim.x + threadIdx.x;
    if (i >= etot) return;
    float x = als[g_srcs[i]] + ald[g_dsts[i]];
    x = (x > 0.f) ? x : LRELU * x;
    g_ew[i] = __float2half_rn(__expf(x));
}

// ---------------------- tf32 helpers ----------------------
__device__ __forceinline__ uint32_t f2tf32(float x) {
    uint32_t r;
    asm("cvt.rna.tf32.f32 %0, %1;" : "=r"(r) : "f"(x));
    return r;
}
#define MMA_TF32(d, a, b) \
    asm volatile("mma.sync.aligned.m16n8k8.row.col.f32.tf32.tf32.f32 " \
        "{%0,%1,%2,%3}, {%4,%5,%6,%7}, {%8,%9}, {%0,%1,%2,%3};" \
        : "+f"((d)[0]), "+f"((d)[1]), "+f"((d)[2]), "+f"((d)[3]) \
        : "r"((a)[0]), "r"((a)[1]), "r"((a)[2]), "r"((a)[3]), \
          "r"((b)[0]), "r"((b)[1]))

template <typename TA>
__device__ __forceinline__ float4 loadA4(const TA* __restrict__ A, size_t elem_off) {
    if constexpr (sizeof(TA) == 4) {
        return *(const float4*)((const float*)A + elem_off);
    } else {
        uint2 u = *(const uint2*)((const __half*)A + elem_off);
        float2 f01 = __half22float2(*(__half2*)&u.x);
        float2 f23 = __half22float2(*(__half2*)&u.y);
        return make_float4(f01.x, f01.y, f23.x, f23.y);
    }
}

// ---------------------- TC GEMM 128x128 + attn coefs (8 heads x 16) ----------------------
template <typename TA>
__global__ __launch_bounds__(256) void k_gemm_attn8_tc(
    const TA* __restrict__ A, const float* __restrict__ W,
    const float* __restrict__ asr, const float* __restrict__ adr,
    __half* __restrict__ H, float* __restrict__ als, float* __restrict__ ald, int n)
{
    __shared__ __align__(16) uint32_t As[128 * 36];
    __shared__ __align__(16) uint32_t Bs[32 * 136];
    int tid = threadIdx.x;
    int wid = tid >> 5, lane = tid & 31;
    int warp_m = wid >> 1, warp_n = wid & 1;
    int g = lane >> 2, c = lane & 3;
    int row0 = blockIdx.x * 128;

    float acc[2][8][4];
    #pragma unroll
    for (int mt = 0; mt < 2; mt++)
        #pragma unroll
        for (int nt = 0; nt < 8; nt++)
            #pragma unroll
            for (int j = 0; j < 4; j++) acc[mt][nt][j] = 0.f;

    for (int k0 = 0; k0 < 128; k0 += 32) {
        #pragma unroll
        for (int l = 0; l < 4; l++) {
            int idx = tid + l * 256;
            int r = idx >> 3, kq = idx & 7;
            int gr = row0 + r;
            float4 v = make_float4(0.f, 0.f, 0.f, 0.f);
            if (gr < n) v = loadA4<TA>(A, (size_t)gr * 128 + k0 + kq * 4);
            uint4 u = {f2tf32(v.x), f2tf32(v.y), f2tf32(v.z), f2tf32(v.w)};
            *(uint4*)&As[r * 36 + kq * 4] = u;
        }
        #pragma unroll
        for (int l = 0; l < 4; l++) {
            int idx = tid + l * 256;
            int kr = idx >> 5, cq = idx & 31;
            float4 v = *(const float4*)(W + (size_t)(k0 + kr) * 128 + cq * 4);
            uint4 u = {f2tf32(v.x), f2tf32(v.y), f2tf32(v.z), f2tf32(v.w)};
            *(uint4*)&Bs[kr * 136 + cq * 4] = u;
        }
        __syncthreads();
        #pragma unroll
        for (int ks = 0; ks < 4; ks++) {
            uint32_t bf[8][2];
            #pragma unroll
            for (int nt = 0; nt < 8; nt++) {
                int col = warp_n * 64 + nt * 8 + g;
                bf[nt][0] = Bs[(ks * 8 + c) * 136 + col];
                bf[nt][1] = Bs[(ks * 8 + c + 4) * 136 + col];
            }
            #pragma unroll
            for (int mt = 0; mt < 2; mt++) {
                int row = warp_m * 32 + mt * 16 + g;
                uint32_t af[4];
                af[0] = As[row * 36 + ks * 8 + c];
                af[1] = As[(row + 8) * 36 + ks * 8 + c];
                af[2] = As[row * 36 + ks * 8 + c + 4];
                af[3] = As[(row + 8) * 36 + ks * 8 + c + 4];
                #pragma unroll
                for (int nt = 0; nt < 8; nt++) MMA_TF32(acc[mt][nt], af, bf[nt]);
            }
        }
        __syncthreads();
    }

    #pragma unroll
    for (int mt = 0; mt < 2; mt++) {
        int r_lo = row0 + warp_m * 32 + mt * 16 + g;
        int r_hi = r_lo + 8;
        float sA0[4] = {0, 0, 0, 0}, sA1[4] = {0, 0, 0, 0};
        float sD0[4] = {0, 0, 0, 0}, sD1[4] = {0, 0, 0, 0};
        #pragma unroll
        for (int nt = 0; nt < 8; nt++) {
            int col = warp_n * 64 + nt * 8 + c * 2;
            int hh = nt >> 1;
            float as0 = asr[col], as1 = asr[col + 1];
            float ad0 = adr[col], ad1 = adr[col + 1];
            float* d = acc[mt][nt];
            sA0[hh] = fmaf(d[0], as0, fmaf(d[1], as1, sA0[hh]));
            sA1[hh] = fmaf(d[2], as0, fmaf(d[3], as1, sA1[hh]));
            sD0[hh] = fmaf(d[0], ad0, fmaf(d[1], ad1, sD0[hh]));
            sD1[hh] = fmaf(d[2], ad0, fmaf(d[3], ad1, sD1[hh]));
            if (r_lo < n) *(__half2*)(H + (size_t)r_lo * 128 + col) = __floats2half2_rn(d[0], d[1]);
            if (r_hi < n) *(__half2*)(H + (size_t)r_hi * 128 + col) = __floats2half2_rn(d[2], d[3]);
        }
        #pragma unroll
        for (int hh = 0; hh < 4; hh++) {
            sA0[hh] += __shfl_xor_sync(0xFFFFFFFFu, sA0[hh], 1);
            sA0[hh] += __shfl_xor_sync(0xFFFFFFFFu, sA0[hh], 2);
            sA1[hh] += __shfl_xor_sync(0xFFFFFFFFu, sA1[hh], 1);
            sA1[hh] += __shfl_xor_sync(0xFFFFFFFFu, sA1[hh], 2);
            sD0[hh] += __shfl_xor_sync(0xFFFFFFFFu, sD0[hh], 1);
            sD0[hh] += __shfl_xor_sync(0xFFFFFFFFu, sD0[hh], 2);
            sD1[hh] += __shfl_xor_sync(0xFFFFFFFFu, sD1[hh], 1);
            sD1[hh] += __shfl_xor_sync(0xFFFFFFFFu, sD1[hh], 2);
        }
        if (c == 0) {
            #pragma unroll
            for (int hh = 0; hh < 4; hh++) {
                int hgl = warp_n * 4 + hh;
                if (r_lo < n) { als[(size_t)r_lo * 8 + hgl] = sA0[hh]; ald[(size_t)r_lo * 8 + hgl] = sD0[hh]; }
                if (r_hi < n) { als[(size_t)r_hi * 8 + hgl] = sA1[hh]; ald[(size_t)r_hi * 8 + hgl] = sD1[hh]; }
            }
        }
    }
}

// ---------------------- TC GEMM 128x64 + attn coefs (1 head x 64) ----------------------
__global__ __launch_bounds__(256) void k_gemm_attn1_tc(
    const __half* __restrict__ A, const float* __restrict__ W,
    const float* __restrict__ asr, const float* __restrict__ adr,
    __half* __restrict__ H, float* __restrict__ als, float* __restrict__ ald, int n)
{
    __shared__ __align__(16) uint32_t As[128 * 36];
    __shared__ __align__(16) uint32_t Bs[32 * 72];
    int tid = threadIdx.x;
    int wid = tid >> 5, lane = tid & 31;
    int g = lane >> 2, c = lane & 3;
    int row0 = blockIdx.x * 128;

    float acc[8][4];
    #pragma unroll
    for (int nt = 0; nt < 8; nt++)
        #pragma unroll
        for (int j = 0; j < 4; j++) acc[nt][j] = 0.f;

    for (int k0 = 0; k0 < 128; k0 += 32) {
        #pragma unroll
        for (int l = 0; l < 4; l++) {
            int idx = tid + l * 256;
            int r = idx >> 3, kq = idx & 7;
            int gr = row0 + r;
            float4 v = make_float4(0.f, 0.f, 0.f, 0.f);
            if (gr < n) v = loadA4<__half>(A, (size_t)gr * 128 + k0 + kq * 4);
            uint4 u = {f2tf32(v.x), f2tf32(v.y), f2tf32(v.z), f2tf32(v.w)};
            *(uint4*)&As[r * 36 + kq * 4] = u;
        }
        #pragma unroll
        for (int l = 0; l < 2; l++) {
            int idx = tid + l * 256;
            int kr = idx >> 4, cq = idx & 15;
            float4 v = *(const float4*)(W + (size_t)(k0 + kr) * 64 + cq * 4);
            uint4 u = {f2tf32(v.x), f2tf32(v.y), f2tf32(v.z), f2tf32(v.w)};
            *(uint4*)&Bs[kr * 72 + cq * 4] = u;
        }
        __syncthreads();
        #pragma unroll
        for (int ks = 0; ks < 4; ks++) {
            int row = wid * 16 + g;
            uint32_t af[4];
            af[0] = As[row * 36 + ks * 8 + c];
            af[1] = As[(row + 8) * 36 + ks * 8 + c];
            af[2] = As[row * 36 + ks * 8 + c + 4];
            af[3] = As[(row + 8) * 36 + ks * 8 + c + 4];
            #pragma unroll
            for (int nt = 0; nt < 8; nt++) {
                int col = nt * 8 + g;
                uint32_t bf[2];
                bf[0] = Bs[(ks * 8 + c) * 72 + col];
                bf[1] = Bs[(ks * 8 + c + 4) * 72 + col];
                MMA_TF32(acc[nt], af, bf);
            }
        }
        __syncthreads();
    }

    int r_lo = row0 + wid * 16 + g;
    int r_hi = r_lo + 8;
    float sA0 = 0.f, sA1 = 0.f, sD0 = 0.f, sD1 = 0.f;
    #pragma unroll
    for (int nt = 0; nt < 8; nt++) {
        int col = nt * 8 + c * 2;
        float as0 = asr[col], as1 = asr[col + 1];
        float ad0 = adr[col], ad1 = adr[col + 1];
        float* d = acc[nt];
        sA0 = fmaf(d[0], as0, fmaf(d[1], as1, sA0));
        sA1 = fmaf(d[2], as0, fmaf(d[3], as1, sA1));
        sD0 = fmaf(d[0], ad0, fmaf(d[1], ad1, sD0));
        sD1 = fmaf(d[2], ad0, fmaf(d[3], ad1, sD1));
        if (r_lo < n) *(__half2*)(H + (size_t)r_lo * 64 + col) = __floats2half2_rn(d[0], d[1]);
        if (r_hi < n) *(__half2*)(H + (size_t)r_hi * 64 + col) = __floats2half2_rn(d[2], d[3]);
    }
    sA0 += __shfl_xor_sync(0xFFFFFFFFu, sA0, 1); sA0 += __shfl_xor_sync(0xFFFFFFFFu, sA0, 2);
    sA1 += __shfl_xor_sync(0xFFFFFFFFu, sA1, 1); sA1 += __shfl_xor_sync(0xFFFFFFFFu, sA1, 2);
    sD0 += __shfl_xor_sync(0xFFFFFFFFu, sD0, 1); sD0 += __shfl_xor_sync(0xFFFFFFFFu, sD0, 2);
    sD1 += __shfl_xor_sync(0xFFFFFFFFu, sD1, 1); sD1 += __shfl_xor_sync(0xFFFFFFFFu, sD1, 2);
    if (c == 0) {
        if (r_lo < n) { als[r_lo] = sA0; ald[r_lo] = sD0; }
        if (r_hi < n) { als[r_hi] = sA1; ald[r_hi] = sD1; }
    }
}

// ---------------------- aggregation (8 heads x 16) + fused LN+ReLU ----------------------
__global__ __launch_bounds__(256) void k_agg8(
    const __half* __restrict__ H, const float* __restrict__ bias,
    const float* __restrict__ lng, const float* __restrict__ lnb,
    __half* __restrict__ out, int n)
{
    int w = (blockIdx.x * blockDim.x + threadIdx.x) >> 5;
    if (w >= n) return;
    int lane = threadIdx.x & 31;
    int s = g_rowptr[w], e2 = g_rowptr[w + 1];
    int hd = lane >> 2;
    int d0 = lane * 4;
    float denom = 0.f;
    float ax = 0.f, ay = 0.f, az = 0.f, aw = 0.f;

    int i = s;
    for (; i + 4 <= e2; i += 4) {
        int sv[4];
        float wv[4];
        #pragma unroll
        for (int j = 0; j < 4; j++) sv[j] = g_srcs[i + j];
        #pragma unroll
        for (int j = 0; j < 4; j++) wv[j] = __half2float(g_ew[(size_t)(i + j) * 8 + hd]);
        uint2 raw[4];
        #pragma unroll
        for (int j = 0; j < 4; j++) raw[j] = *(const uint2*)(H + (size_t)sv[j] * 128 + d0);
        #pragma unroll
        for (int j = 0; j < 4; j++) {
            denom += wv[j];
            float2 f01 = __half22float2(*(__half2*)&raw[j].x);
            float2 f23 = __half22float2(*(__half2*)&raw[j].y);
            ax = fmaf(wv[j], f01.x, ax); ay = fmaf(wv[j], f01.y, ay);
            az = fmaf(wv[j], f23.x, az); aw = fmaf(wv[j], f23.y, aw);
        }
    }
    for (; i < e2; ++i) {
        int s0 = g_srcs[i];
        float w0 = __half2float(g_ew[(size_t)i * 8 + hd]);
        denom += w0;
        uint2 raw = *(const uint2*)(H + (size_t)s0 * 128 + d0);
        float2 f01 = __half22float2(*(__half2*)&raw.x);
        float2 f23 = __half22float2(*(__half2*)&raw.y);
        ax = fmaf(w0, f01.x, ax); ay = fmaf(w0, f01.y, ay);
        az = fmaf(w0, f23.x, az); aw = fmaf(w0, f23.y, aw);
    }

    float inv = 1.f / denom;
    float4 bv = *(const float4*)(bias + d0);
    float ox = fmaf(ax, inv, bv.x);
    float oy = fmaf(ay, inv, bv.y);
    float oz = fmaf(az, inv, bv.z);
    float ow = fmaf(aw, inv, bv.w);

    float sm = ox + oy + oz + ow;
    #pragma unroll
    for (int o = 16; o; o >>= 1) sm += __shfl_xor_sync(0xFFFFFFFFu, sm, o);
    float mu = sm * (1.f / 128.f);
    float dx = ox - mu, dy = oy - mu, dz = oz - mu, dw = ow - mu;
    float q = dx * dx + dy * dy + dz * dz + dw * dw;
    #pragma unroll
    for (int o = 16; o; o >>= 1) q += __shfl_xor_sync(0xFFFFFFFFu, q, o);
    float rstd = rsqrtf(q * (1.f / 128.f) + 1e-5f);
    float4 gg = *(const float4*)(lng + d0);
    float4 bb = *(const float4*)(lnb + d0);
    ox = fmaxf(fmaf(dx * rstd, gg.x, bb.x), 0.f);
    oy = fmaxf(fmaf(dy * rstd, gg.y, bb.y), 0.f);
    oz = fmaxf(fmaf(dz * rstd, gg.z, bb.z), 0.f);
    ow = fmaxf(fmaf(dw * rstd, gg.w, bb.w), 0.f);

    __half2 h01 = __floats2half2_rn(ox, oy);
    __half2 h23 = __floats2half2_rn(oz, ow);
    uint2 packed = {*(uint32_t*)&h01, *(uint32_t*)&h23};
    *(uint2*)(out + (size_t)w * 128 + d0) = packed;
}

// ---------------------- aggregation (1 head x 64) + log_softmax ----------------------
__global__ __launch_bounds__(256) void k_agg1_lsm(
    const __half* __restrict__ H, const float* __restrict__ bias,
    float* __restrict__ out, int n)
{
    int w = (blockIdx.x * blockDim.x + threadIdx.x) >> 5;
    if (w >= n) return;
    int lane = threadIdx.x & 31;
    int s = g_rowptr[w], e2 = g_rowptr[w + 1];
    int d0 = lane * 2;

    float denom = 0.f, acc0 = 0.f, acc1 = 0.f;
    int i = s;
    for (; i + 4 <= e2; i += 4) {
        int sv[4];
        float wv[4];
        #pragma unroll
        for (int j = 0; j < 4; j++) sv[j] = g_srcs[i + j];
        #pragma unroll
        for (int j = 0; j < 4; j++) wv[j] = __half2float(g_ew[i + j]);
        __half2 hv[4];
        #pragma unroll
        for (int j = 0; j < 4; j++) hv[j] = *(const __half2*)(H + (size_t)sv[j] * 64 + d0);
        #pragma unroll
        for (int j = 0; j < 4; j++) {
            denom += wv[j];
            float2 f = __half22float2(hv[j]);
            acc0 = fmaf(wv[j], f.x, acc0);
            acc1 = fmaf(wv[j], f.y, acc1);
        }
    }
    for (; i < e2; ++i) {
        int s0 = g_srcs[i];
        float w0 = __half2float(g_ew[i]);
        denom += w0;
        float2 f = __half22float2(*(const __half2*)(H + (size_t)s0 * 64 + d0));
        acc0 = fmaf(w0, f.x, acc0); acc1 = fmaf(w0, f.y, acc1);
    }
    float inv = 1.f / denom;
    float v0 = fmaf(acc0, inv, bias[d0]);
    float v1 = fmaf(acc1, inv, bias[d0 + 1]);
    float mx = fmaxf(v0, v1);
    #pragma unroll
    for (int o = 16; o; o >>= 1) mx = fmaxf(mx, __shfl_xor_sync(0xFFFFFFFFu, mx, o));
    float se = __expf(v0 - mx) + __expf(v1 - mx);
    #pragma unroll
    for (int o = 16; o; o >>= 1) se += __shfl_xor_sync(0xFFFFFFFFu, se, o);
    float lse = mx + __logf(se);
    out[(size_t)w * 64 + d0] = v0 - lse;
    out[(size_t)w * 64 + d0 + 1] = v1 - lse;
}

// ---------------------- launcher ----------------------
extern "C" void kernel_launch(void* const* d_in, const int* in_sizes, int n_in,
                              void* d_out, int out_size) {
    const float* x   = (const float*)d_in[0];
    const int*   ei  = (const int*)d_in[1];
    const float* W0  = (const float*)d_in[2];
    const float* as0 = (const float*)d_in[3];
    const float* ad0 = (const float*)d_in[4];
    const float* b0  = (const float*)d_in[5];
    const float* W1  = (const float*)d_in[6];
    const float* as1 = (const float*)d_in[7];
    const float* ad1 = (const float*)d_in[8];
    const float* b1  = (const float*)d_in[9];
    const float* W2  = (const float*)d_in[10];
    const float* as2 = (const float*)d_in[11];
    const float* ad2 = (const float*)d_in[12];
    const float* b2  = (const float*)d_in[13];
    const float* ln1g = (const float*)d_in[14];
    const float* ln1b = (const float*)d_in[15];
    const float* ln2g = (const float*)d_in[16];
    const float* ln2b = (const float*)d_in[17];
    float* out = (float*)d_out;

    const int n = in_sizes[0] / 128;
    const int e = in_sizes[1] / 2;
    const int etot = e + n;
    const int* src = ei;
    const int* dst = ei + e;

    __half *h, *feat;
    float *als, *ald;
    cudaGetSymbolAddress((void**)&h, g_h);
    cudaGetSymbolAddress((void**)&feat, g_feat);
    cudaGetSymbolAddress((void**)&als, g_als);
    cudaGetSymbolAddress((void**)&ald, g_ald);

    const int nb_nodes256 = (n + 255) / 256;
    const int nb_edges256 = (e + 255) / 256;
    const int nb_etot256 = (etot + 255) / 256;
    const int nb_scan = (n + 1023) / 1024;
    const int nb_warp = (n * 32 + 255) / 256;
    const int nb_gemm = (n + 127) / 128;

    // CSR build starts on the default stream
    k_init_cnt<<<nb_nodes256, 256>>>(n);                      // launch 1
    k_count<<<nb_edges256, 256>>>(dst, e);                    // launch 2
    k_scan1<<<nb_scan, 1024>>>(n);                            // launch 3

    // fork: gemm0 is independent of the CSR build — overlap it on stream B
    cudaEventRecord(g_evFork, 0);
    cudaStreamWaitEvent(g_sB, g_evFork, 0);
    k_gemm_attn8_tc<float><<<nb_gemm, 256, 0, g_sB>>>(x, W0, as0, ad0, h, als, ald, n);  // launch 4 (ncu slot)

    k_scan2<<<1, 128>>>(nb_scan);                             // launch 5
    k_scan3<<<nb_scan, 1024>>>(n, etot);                      // launch 6
    k_scatter<<<nb_edges256, 256>>>(src, dst, e);             // launch 7

    // join: edgew needs both CSR (default) and gemm0 (stream B)
    cudaEventRecord(g_evJoin, g_sB);
    cudaStreamWaitEvent(0, g_evJoin, 0);

    k_edgew8<<<nb_etot256, 256>>>(als, ald, etot);            // launch 8
    k_agg8<<<nb_warp, 256>>>(h, b0, ln1g, ln1b, feat, n);     // launch 9

    k_gemm_attn8_tc<__half><<<nb_gemm, 256>>>(feat, W1, as1, ad1, h, als, ald, n);  // 10
    k_edgew8<<<nb_etot256, 256>>>(als, ald, etot);            // 11
    k_agg8<<<nb_warp, 256>>>(h, b1, ln2g, ln2b, feat, n);     // 12

    k_gemm_attn1_tc<<<nb_gemm, 256>>>(feat, W2, as2, ad2, h, als, ald, n);          // 13
    k_edgew1<<<nb_etot256, 256>>>(als, ald, etot);            // 14
    k_agg1_lsm<<<nb_warp, 256>>>(h, b2, out, n);              // 15
}

// round 10
// speedup vs baseline: 1.0816x; 1.0175x over previous
#include <cuda_runtime.h>
#include <cuda_fp16.h>
#include <math.h>
#include <stdint.h>

#define NN 100000
#define NE 1600000
#define ET (NE + NN)
#define LRELU 0.2f

// ---------- scratch ----------
__device__ __half g_h[(size_t)NN * 128];
__device__ __half g_feat[(size_t)NN * 128];
__device__ float g_als[(size_t)NN * 8];
__device__ float g_ald[(size_t)NN * 8];
__device__ __half g_ew[(size_t)ET * 8];
__device__ int   g_rowptr[NN + 1];
__device__ int   g_cnt[NN];
__device__ int   g_srcs[ET];
__device__ int   g_dsts[ET];
__device__ int   g_part[128];

// ---------- side stream ----------
static cudaStream_t g_sB;
static cudaEvent_t g_evFork, g_evJoin;
namespace {
struct StreamInit {
    StreamInit() {
        cudaStreamCreateWithFlags(&g_sB, cudaStreamNonBlocking);
        cudaEventCreateWithFlags(&g_evFork, cudaEventDisableTiming);
        cudaEventCreateWithFlags(&g_evJoin, cudaEventDisableTiming);
    }
};
StreamInit g_streamInit;
}

// ---------------------- CSR build ----------------------
__global__ void k_init_cnt(int n) {
    int i = blockIdx.x * blockDim.x + threadIdx.x;
    if (i < n) g_cnt[i] = 1;
}
__global__ void k_count(const int* __restrict__ dst, int e) {
    int i = blockIdx.x * blockDim.x + threadIdx.x;
    if (i < e) atomicAdd(&g_cnt[dst[i]], 1);
}
__global__ void k_scan1(int n) {
    __shared__ int sh[1024];
    int tid = threadIdx.x;
    int i = blockIdx.x * 1024 + tid;
    int v = (i < n) ? g_cnt[i] : 0;
    sh[tid] = v;
    __syncthreads();
    #pragma unroll
    for (int o = 1; o < 1024; o <<= 1) {
        int t = (tid >= o) ? sh[tid - o] : 0;
        __syncthreads();
        sh[tid] += t;
        __syncthreads();
    }
    if (i < n) g_rowptr[i] = sh[tid] - v;
    if (tid == 1023) g_part[blockIdx.x] = sh[1023];
}
__global__ void k_scan2(int nb) {
    __shared__ int sh[128];
    int tid = threadIdx.x;
    int v = (tid < nb) ? g_part[tid] : 0;
    sh[tid] = v;
    __syncthreads();
    #pragma unroll
    for (int o = 1; o < 128; o <<= 1) {
        int t = (tid >= o) ? sh[tid - o] : 0;
        __syncthreads();
        sh[tid] += t;
        __syncthreads();
    }
    if (tid < nb) g_part[tid] = sh[tid] - v;
}
__global__ void k_scan3(int n, int etot) {
    int i = blockIdx.x * 1024 + threadIdx.x;
    if (i < n) {
        int p = g_rowptr[i] + g_part[blockIdx.x];
        g_rowptr[i] = p;
        g_srcs[p] = i;
        g_dsts[p] = i;
        g_cnt[i] = p + 1;
    }
    if (i == 0) g_rowptr[n] = etot;
}
__global__ void k_scatter(const int* __restrict__ src, const int* __restrict__ dst, int e) {
    int i = blockIdx.x * blockDim.x + threadIdx.x;
    if (i < e) {
        int d = dst[i];
        int pos = atomicAdd(&g_cnt[d], 1);
        g_srcs[pos] = src[i];
        g_dsts[pos] = d;
    }
}

// ---------------------- edge weight precompute ----------------------
__global__ __launch_bounds__(256) void k_edgew8(const float* __restrict__ als,
                                                const float* __restrict__ ald,
                                                int etot) {
    int i = blockIdx.x * blockDim.x + threadIdx.x;
    if (i >= etot) return;
    int s = g_srcs[i], d = g_dsts[i];
    float4 a0 = *(const float4*)(als + (size_t)s * 8);
    float4 a1 = *(const float4*)(als + (size_t)s * 8 + 4);
    float4 b0 = *(const float4*)(ald + (size_t)d * 8);
    float4 b1 = *(const float4*)(ald + (size_t)d * 8 + 4);
    float x[8] = {a0.x + b0.x, a0.y + b0.y, a0.z + b0.z, a0.w + b0.w,
                  a1.x + b1.x, a1.y + b1.y, a1.z + b1.z, a1.w + b1.w};
    __half hw[8];
    #pragma unroll
    for (int h = 0; h < 8; h++) {
        float v = (x[h] > 0.f) ? x[h] : LRELU * x[h];
        hw[h] = __float2half_rn(__expf(v));
    }
    *(uint4*)(g_ew + (size_t)i * 8) = *(uint4*)hw;
}
__global__ __launch_bounds__(256) void k_edgew1(const float* __restrict__ als,
                                                const float* __restrict__ ald,
                                                int etot) {
    int i = blockIdx.x * blockDim.x + threadIdx.x;
    if (i >= etot) return;
    float x = als[g_srcs[i]] + ald[g_dsts[i]];
    x = (x > 0.f) ? x : LRELU * x;
    g_ew[i] = __float2half_rn(__expf(x));
}

// ---------------------- fp16 mma helper ----------------------
#define MMA_F16(d, a, b) \
    asm volatile("mma.sync.aligned.m16n8k16.row.col.f32.f16.f16.f32 " \
        "{%0,%1,%2,%3}, {%4,%5,%6,%7}, {%8,%9}, {%0,%1,%2,%3};" \
        : "+f"((d)[0]), "+f"((d)[1]), "+f"((d)[2]), "+f"((d)[3]) \
        : "r"((a)[0]), "r"((a)[1]), "r"((a)[2]), "r"((a)[3]), \
          "r"((b)[0]), "r"((b)[1]))

// stage one 32-K chunk of A (128 rows) as half2, row stride 20 u32
template <typename TA>
__device__ __forceinline__ void stage_A16(const TA* __restrict__ A, uint32_t* As32,
                                          int row0, int k0, int n, int tid) {
    #pragma unroll
    for (int l = 0; l < 8; l++) {
        int idx = tid + l * 256;          // 0..2047
        int r = idx >> 4, kq = idx & 15;  // kq = half2 index (k = kq*2)
        int gr = row0 + r;
        uint32_t u = 0;
        if (gr < n) {
            if constexpr (sizeof(TA) == 4) {
                float2 f = *(const float2*)((const float*)A + (size_t)gr * 128 + k0 + kq * 2);
                __half2 h = __floats2half2_rn(f.x, f.y);
                u = *(uint32_t*)&h;
            } else {
                u = *(const uint32_t*)((const __half*)A + (size_t)gr * 128 + k0 + kq * 2);
            }
        }
        As32[r * 20 + kq] = u;
    }
}

// ---------------------- fp16 TC GEMM 128x128 + attn coefs (8 heads x 16) ----------------------
template <typename TA>
__global__ __launch_bounds__(256) void k_gemm_attn8_tc(
    const TA* __restrict__ A, const float* __restrict__ W,
    const float* __restrict__ asr, const float* __restrict__ adr,
    __half* __restrict__ H, float* __restrict__ als, float* __restrict__ ald, int n)
{
    __shared__ __align__(16) uint32_t As32[128 * 20];  // half2[row][16 kpairs], pad 20
    __shared__ __align__(16) uint32_t Bs32[128 * 20];  // half2[col][16 kpairs], pad 20
    int tid = threadIdx.x;
    int wid = tid >> 5, lane = tid & 31;
    int warp_m = wid >> 1, warp_n = wid & 1;
    int g = lane >> 2, c = lane & 3;
    int row0 = blockIdx.x * 128;

    float acc[2][8][4];
    #pragma unroll
    for (int mt = 0; mt < 2; mt++)
        #pragma unroll
        for (int nt = 0; nt < 8; nt++)
            #pragma unroll
            for (int j = 0; j < 4; j++) acc[mt][nt][j] = 0.f;

    for (int k0 = 0; k0 < 128; k0 += 32) {
        stage_A16<TA>(A, As32, row0, k0, n, tid);
        // B: Bs32[col][kp] = half2(W[k0+2kp][col], W[k0+2kp+1][col])
        #pragma unroll
        for (int l = 0; l < 8; l++) {
            int idx = tid + l * 256;      // 0..2047
            int col = idx & 127, kp = idx >> 7;
            float w0 = W[(size_t)(k0 + kp * 2) * 128 + col];
            float w1 = W[(size_t)(k0 + kp * 2 + 1) * 128 + col];
            __half2 h = __floats2half2_rn(w0, w1);
            Bs32[col * 20 + kp] = *(uint32_t*)&h;
        }
        __syncthreads();
        #pragma unroll
        for (int ks = 0; ks < 2; ks++) {
            int kb = ks * 8;
            uint32_t bf[8][2];
            #pragma unroll
            for (int nt = 0; nt < 8; nt++) {
                int col = warp_n * 64 + nt * 8 + g;
                bf[nt][0] = Bs32[col * 20 + kb + c];
                bf[nt][1] = Bs32[col * 20 + kb + c + 4];
            }
            #pragma unroll
            for (int mt = 0; mt < 2; mt++) {
                int row = warp_m * 32 + mt * 16 + g;
                uint32_t af[4];
                af[0] = As32[row * 20 + kb + c];
                af[1] = As32[(row + 8) * 20 + kb + c];
                af[2] = As32[row * 20 + kb + c + 4];
                af[3] = As32[(row + 8) * 20 + kb + c + 4];
                #pragma unroll
                for (int nt = 0; nt < 8; nt++) MMA_F16(acc[mt][nt], af, bf[nt]);
            }
        }
        __syncthreads();
    }

    #pragma unroll
    for (int mt = 0; mt < 2; mt++) {
        int r_lo = row0 + warp_m * 32 + mt * 16 + g;
        int r_hi = r_lo + 8;
        float sA0[4] = {0, 0, 0, 0}, sA1[4] = {0, 0, 0, 0};
        float sD0[4] = {0, 0, 0, 0}, sD1[4] = {0, 0, 0, 0};
        #pragma unroll
        for (int nt = 0; nt < 8; nt++) {
            int col = warp_n * 64 + nt * 8 + c * 2;
            int hh = nt >> 1;
            float as0 = asr[col], as1 = asr[col + 1];
            float ad0 = adr[col], ad1 = adr[col + 1];
            float* d = acc[mt][nt];
            sA0[hh] = fmaf(d[0], as0, fmaf(d[1], as1, sA0[hh]));
            sA1[hh] = fmaf(d[2], as0, fmaf(d[3], as1, sA1[hh]));
            sD0[hh] = fmaf(d[0], ad0, fmaf(d[1], ad1, sD0[hh]));
            sD1[hh] = fmaf(d[2], ad0, fmaf(d[3], ad1, sD1[hh]));
            if (r_lo < n) *(__half2*)(H + (size_t)r_lo * 128 + col) = __floats2half2_rn(d[0], d[1]);
            if (r_hi < n) *(__half2*)(H + (size_t)r_hi * 128 + col) = __floats2half2_rn(d[2], d[3]);
        }
        #pragma unroll
        for (int hh = 0; hh < 4; hh++) {
            sA0[hh] += __shfl_xor_sync(0xFFFFFFFFu, sA0[hh], 1);
            sA0[hh] += __shfl_xor_sync(0xFFFFFFFFu, sA0[hh], 2);
            sA1[hh] += __shfl_xor_sync(0xFFFFFFFFu, sA1[hh], 1);
            sA1[hh] += __shfl_xor_sync(0xFFFFFFFFu, sA1[hh], 2);
            sD0[hh] += __shfl_xor_sync(0xFFFFFFFFu, sD0[hh], 1);
            sD0[hh] += __shfl_xor_sync(0xFFFFFFFFu, sD0[hh], 2);
            sD1[hh] += __shfl_xor_sync(0xFFFFFFFFu, sD1[hh], 1);
            sD1[hh] += __shfl_xor_sync(0xFFFFFFFFu, sD1[hh], 2);
        }
        if (c == 0) {
            #pragma unroll
            for (int hh = 0; hh < 4; hh++) {
                int hgl = warp_n * 4 + hh;
                if (r_lo < n) { als[(size_t)r_lo * 8 + hgl] = sA0[hh]; ald[(size_t)r_lo * 8 + hgl] = sD0[hh]; }
                if (r_hi < n) { als[(size_t)r_hi * 8 + hgl] = sA1[hh]; ald[(size_t)r_hi * 8 + hgl] = sD1[hh]; }
            }
        }
    }
}

// ---------------------- fp16 TC GEMM 128x64 + attn coefs (1 head x 64) ----------------------
__global__ __launch_bounds__(256) void k_gemm_attn1_tc(
    const __half* __restrict__ A, const float* __restrict__ W,
    const float* __restrict__ asr, const float* __restrict__ adr,
    __half* __restrict__ H, float* __restrict__ als, float* __restrict__ ald, int n)
{
    __shared__ __align__(16) uint32_t As32[128 * 20];
    __shared__ __align__(16) uint32_t Bs32[64 * 20];
    int tid = threadIdx.x;
    int wid = tid >> 5, lane = tid & 31;
    int g = lane >> 2, c = lane & 3;
    int row0 = blockIdx.x * 128;

    float acc[8][4];
    #pragma unroll
    for (int nt = 0; nt < 8; nt++)
        #pragma unroll
        for (int j = 0; j < 4; j++) acc[nt][j] = 0.f;

    for (int k0 = 0; k0 < 128; k0 += 32) {
        stage_A16<__half>(A, As32, row0, k0, n, tid);
        #pragma unroll
        for (int l = 0; l < 4; l++) {
            int idx = tid + l * 256;      // 0..1023
            int col = idx & 63, kp = idx >> 6;
            float w0 = W[(size_t)(k0 + kp * 2) * 64 + col];
            float w1 = W[(size_t)(k0 + kp * 2 + 1) * 64 + col];
            __half2 h = __floats2half2_rn(w0, w1);
            Bs32[col * 20 + kp] = *(uint32_t*)&h;
        }
        __syncthreads();
        #pragma unroll
        for (int ks = 0; ks < 2; ks++) {
            int kb = ks * 8;
            int row = wid * 16 + g;
            uint32_t af[4];
            af[0] = As32[row * 20 + kb + c];
            af[1] = As32[(row + 8) * 20 + kb + c];
            af[2] = As32[row * 20 + kb + c + 4];
            af[3] = As32[(row + 8) * 20 + kb + c + 4];
            #pragma unroll
            for (int nt = 0; nt < 8; nt++) {
                int col = nt * 8 + g;
                uint32_t bf[2];
                bf[0] = Bs32[col * 20 + kb + c];
                bf[1] = Bs32[col * 20 + kb + c + 4];
                MMA_F16(acc[nt], af, bf);
            }
        }
        __syncthreads();
    }

    int r_lo = row0 + wid * 16 + g;
    int r_hi = r_lo + 8;
    float sA0 = 0.f, sA1 = 0.f, sD0 = 0.f, sD1 = 0.f;
    #pragma unroll
    for (int nt = 0; nt < 8; nt++) {
        int col = nt * 8 + c * 2;
        float as0 = asr[col], as1 = asr[col + 1];
        float ad0 = adr[col], ad1 = adr[col + 1];
        float* d = acc[nt];
        sA0 = fmaf(d[0], as0, fmaf(d[1], as1, sA0));
        sA1 = fmaf(d[2], as0, fmaf(d[3], as1, sA1));
        sD0 = fmaf(d[0], ad0, fmaf(d[1], ad1, sD0));
        sD1 = fmaf(d[2], ad0, fmaf(d[3], ad1, sD1));
        if (r_lo < n) *(__half2*)(H + (size_t)r_lo * 64 + col) = __floats2half2_rn(d[0], d[1]);
        if (r_hi < n) *(__half2*)(H + (size_t)r_hi * 64 + col) = __floats2half2_rn(d[2], d[3]);
    }
    sA0 += __shfl_xor_sync(0xFFFFFFFFu, sA0, 1); sA0 += __shfl_xor_sync(0xFFFFFFFFu, sA0, 2);
    sA1 += __shfl_xor_sync(0xFFFFFFFFu, sA1, 1); sA1 += __shfl_xor_sync(0xFFFFFFFFu, sA1, 2);
    sD0 += __shfl_xor_sync(0xFFFFFFFFu, sD0, 1); sD0 += __shfl_xor_sync(0xFFFFFFFFu, sD0, 2);
    sD1 += __shfl_xor_sync(0xFFFFFFFFu, sD1, 1); sD1 += __shfl_xor_sync(0xFFFFFFFFu, sD1, 2);
    if (c == 0) {
        if (r_lo < n) { als[r_lo] = sA0; ald[r_lo] = sD0; }
        if (r_hi < n) { als[r_hi] = sA1; ald[r_hi] = sD1; }
    }
}

// ---------------------- aggregation (8 heads x 16) + fused LN+ReLU ----------------------
__global__ __launch_bounds__(256) void k_agg8(
    const __half* __restrict__ H, const float* __restrict__ bias,
    const float* __restrict__ lng, const float* __restrict__ lnb,
    __half* __restrict__ out, int n)
{
    int w = (blockIdx.x * blockDim.x + threadIdx.x) >> 5;
    if (w >= n) return;
    int lane = threadIdx.x & 31;
    int s = g_rowptr[w], e2 = g_rowptr[w + 1];
    int hd = lane >> 2;
    int d0 = lane * 4;
    float denom = 0.f;
    float ax = 0.f, ay = 0.f, az = 0.f, aw = 0.f;

    int i = s;
    for (; i + 4 <= e2; i += 4) {
        int sv[4];
        float wv[4];
        #pragma unroll
        for (int j = 0; j < 4; j++) sv[j] = g_srcs[i + j];
        #pragma unroll
        for (int j = 0; j < 4; j++) wv[j] = __half2float(g_ew[(size_t)(i + j) * 8 + hd]);
        uint2 raw[4];
        #pragma unroll
        for (int j = 0; j < 4; j++) raw[j] = *(const uint2*)(H + (size_t)sv[j] * 128 + d0);
        #pragma unroll
        for (int j = 0; j < 4; j++) {
            denom += wv[j];
            float2 f01 = __half22float2(*(__half2*)&raw[j].x);
            float2 f23 = __half22float2(*(__half2*)&raw[j].y);
            ax = fmaf(wv[j], f01.x, ax); ay = fmaf(wv[j], f01.y, ay);
            az = fmaf(wv[j], f23.x, az); aw = fmaf(wv[j], f23.y, aw);
        }
    }
    for (; i < e2; ++i) {
        int s0 = g_srcs[i];
        float w0 = __half2float(g_ew[(size_t)i * 8 + hd]);
        denom += w0;
        uint2 raw = *(const uint2*)(H + (size_t)s0 * 128 + d0);
        float2 f01 = __half22float2(*(__half2*)&raw.x);
        float2 f23 = __half22float2(*(__half2*)&raw.y);
        ax = fmaf(w0, f01.x, ax); ay = fmaf(w0, f01.y, ay);
        az = fmaf(w0, f23.x, az); aw = fmaf(w0, f23.y, aw);
    }

    float inv = 1.f / denom;
    float4 bv = *(const float4*)(bias + d0);
    float ox = fmaf(ax, inv, bv.x);
    float oy = fmaf(ay, inv, bv.y);
    float oz = fmaf(az, inv, bv.z);
    float ow = fmaf(aw, inv, bv.w);

    float sm = ox + oy + oz + ow;
    #pragma unroll
    for (int o = 16; o; o >>= 1) sm += __shfl_xor_sync(0xFFFFFFFFu, sm, o);
    float mu = sm * (1.f / 128.f);
    float dx = ox - mu, dy = oy - mu, dz = oz - mu, dw = ow - mu;
    float q = dx * dx + dy * dy + dz * dz + dw * dw;
    #pragma unroll
    for (int o = 16; o; o >>= 1) q += __shfl_xor_sync(0xFFFFFFFFu, q, o);
    float rstd = rsqrtf(q * (1.f / 128.f) + 1e-5f);
    float4 gg = *(const float4*)(lng + d0);
    float4 bb = *(const float4*)(lnb + d0);
    ox = fmaxf(fmaf(dx * rstd, gg.x, bb.x), 0.f);
    oy = fmaxf(fmaf(dy * rstd, gg.y, bb.y), 0.f);
    oz = fmaxf(fmaf(dz * rstd, gg.z, bb.z), 0.f);
    ow = fmaxf(fmaf(dw * rstd, gg.w, bb.w), 0.f);

    __half2 h01 = __floats2half2_rn(ox, oy);
    __half2 h23 = __floats2half2_rn(oz, ow);
    uint2 packed = {*(uint32_t*)&h01, *(uint32_t*)&h23};
    *(uint2*)(out + (size_t)w * 128 + d0) = packed;
}

// ---------------------- aggregation (1 head x 64) + log_softmax ----------------------
__global__ __launch_bounds__(256) void k_agg1_lsm(
    const __half* __restrict__ H, const float* __restrict__ bias,
    float* __restrict__ out, int n)
{
    int w = (blockIdx.x * blockDim.x + threadIdx.x) >> 5;
    if (w >= n) return;
    int lane = threadIdx.x & 31;
    int s = g_rowptr[w], e2 = g_rowptr[w + 1];
    int d0 = lane * 2;

    float denom = 0.f, acc0 = 0.f, acc1 = 0.f;
    int i = s;
    for (; i + 4 <= e2; i += 4) {
        int sv[4];
        float wv[4];
        #pragma unroll
        for (int j = 0; j < 4; j++) sv[j] = g_srcs[i + j];
        #pragma unroll
        for (int j = 0; j < 4; j++) wv[j] = __half2float(g_ew[i + j]);
        __half2 hv[4];
        #pragma unroll
        for (int j = 0; j < 4; j++) hv[j] = *(const __half2*)(H + (size_t)sv[j] * 64 + d0);
        #pragma unroll
        for (int j = 0; j < 4; j++) {
            denom += wv[j];
            float2 f = __half22float2(hv[j]);
            acc0 = fmaf(wv[j], f.x, acc0);
            acc1 = fmaf(wv[j], f.y, acc1);
        }
    }
    for (; i < e2; ++i) {
        int s0 = g_srcs[i];
        float w0 = __half2float(g_ew[i]);
        denom += w0;
        float2 f = __half22float2(*(const __half2*)(H + (size_t)s0 * 64 + d0));
        acc0 = fmaf(w0, f.x, acc0); acc1 = fmaf(w0, f.y, acc1);
    }
    float inv = 1.f / denom;
    float v0 = fmaf(acc0, inv, bias[d0]);
    float v1 = fmaf(acc1, inv, bias[d0 + 1]);
    float mx = fmaxf(v0, v1);
    #pragma unroll
    for (int o = 16; o; o >>= 1) mx = fmaxf(mx, __shfl_xor_sync(0xFFFFFFFFu, mx, o));
    float se = __expf(v0 - mx) + __expf(v1 - mx);
    #pragma unroll
    for (int o = 16; o; o >>= 1) se += __shfl_xor_sync(0xFFFFFFFFu, se, o);
    float lse = mx + __logf(se);
    out[(size_t)w * 64 + d0] = v0 - lse;
    out[(size_t)w * 64 + d0 + 1] = v1 - lse;
}

// ---------------------- launcher ----------------------
extern "C" void kernel_launch(void* const* d_in, const int* in_sizes, int n_in,
                              void* d_out, int out_size) {
    const float* x   = (const float*)d_in[0];
    const int*   ei  = (const int*)d_in[1];
    const float* W0  = (const float*)d_in[2];
    const float* as0 = (const float*)d_in[3];
    const float* ad0 = (const float*)d_in[4];
    const float* b0  = (const float*)d_in[5];
    const float* W1  = (const float*)d_in[6];
    const float* as1 = (const float*)d_in[7];
    const float* ad1 = (const float*)d_in[8];
    const float* b1  = (const float*)d_in[9];
    const float* W2  = (const float*)d_in[10];
    const float* as2 = (const float*)d_in[11];
    const float* ad2 = (const float*)d_in[12];
    const float* b2  = (const float*)d_in[13];
    const float* ln1g = (const float*)d_in[14];
    const float* ln1b = (const float*)d_in[15];
    const float* ln2g = (const float*)d_in[16];
    const float* ln2b = (const float*)d_in[17];
    float* out = (float*)d_out;

    const int n = in_sizes[0] / 128;
    const int e = in_sizes[1] / 2;
    const int etot = e + n;
    const int* src = ei;
    const int* dst = ei + e;

    __half *h, *feat;
    float *als, *ald;
    cudaGetSymbolAddress((void**)&h, g_h);
    cudaGetSymbolAddress((void**)&feat, g_feat);
    cudaGetSymbolAddress((void**)&als, g_als);
    cudaGetSymbolAddress((void**)&ald, g_ald);

    const int nb_nodes256 = (n + 255) / 256;
    const int nb_edges256 = (e + 255) / 256;
    const int nb_etot256 = (etot + 255) / 256;
    const int nb_scan = (n + 1023) / 1024;
    const int nb_warp = (n * 32 + 255) / 256;
    const int nb_gemm = (n + 127) / 128;

    k_init_cnt<<<nb_nodes256, 256>>>(n);
    k_count<<<nb_edges256, 256>>>(dst, e);
    k_scan1<<<nb_scan, 1024>>>(n);

    cudaEventRecord(g_evFork, 0);
    cudaStreamWaitEvent(g_sB, g_evFork, 0);
    k_gemm_attn8_tc<float><<<nb_gemm, 256, 0, g_sB>>>(x, W0, as0, ad0, h, als, ald, n);  // ncu slot 4

    k_scan2<<<1, 128>>>(nb_scan);
    k_scan3<<<nb_scan, 1024>>>(n, etot);
    k_scatter<<<nb_edges256, 256>>>(src, dst, e);

    cudaEventRecord(g_evJoin, g_sB);
    cudaStreamWaitEvent(0, g_evJoin, 0);

    k_edgew8<<<nb_etot256, 256>>>(als, ald, etot);
    k_agg8<<<nb_warp, 256>>>(h, b0, ln1g, ln1b, feat, n);

    k_gemm_attn8_tc<__half><<<nb_gemm, 256>>>(feat, W1, as1, ad1, h, als, ald, n);
    k_edgew8<<<nb_etot256, 256>>>(als, ald, etot);
    k_agg8<<<nb_warp, 256>>>(h, b1, ln2g, ln2b, feat, n);

    k_gemm_attn1_tc<<<nb_gemm, 256>>>(feat, W2, as2, ad2, h, als, ald, n);
    k_edgew1<<<nb_etot256, 256>>>(als, ald, etot);
    k_agg1_lsm<<<nb_warp, 256>>>(h, b2, out, n);
}

// round 12
// speedup vs baseline: 1.1546x; 1.0675x over previous
#include <cuda_runtime.h>
#include <cuda_fp16.h>
#include <math.h>
#include <stdint.h>

#define NN 100000
#define NE 1600000
#define ET (NE + NN)
#define LRELU 0.2f

// ---------- scratch ----------
__device__ __half g_h[(size_t)NN * 128];
__device__ __half g_feat[(size_t)NN * 128];
__device__ __half g_x16[(size_t)NN * 128];
__device__ uint32_t g_w0t[128 * 64];   // W0 fp16, [col][kpair]
__device__ uint32_t g_w1t[128 * 64];
__device__ uint32_t g_w2t[64 * 64];
__device__ float g_als[(size_t)NN * 8];
__device__ float g_ald[(size_t)NN * 8];
__device__ __half g_ew[(size_t)ET * 8];
__device__ int   g_rowptr[NN + 1];
__device__ int   g_cnt[NN];
__device__ int   g_srcs[ET];
__device__ int   g_dsts[ET];
__device__ int   g_part[128];

// ---------- forward decls for attribute setup ----------
__global__ void k_gemm8(const __half* __restrict__, const uint32_t* __restrict__,
                        const float* __restrict__, const float* __restrict__,
                        __half* __restrict__, float* __restrict__, float* __restrict__, int);
__global__ void k_gemm1(const __half* __restrict__, const uint32_t* __restrict__,
                        const float* __restrict__, const float* __restrict__,
                        __half* __restrict__, float* __restrict__, float* __restrict__, int);

#define SMEM8 (2 * 128 * 68 * 4)
#define SMEM1 ((128 * 68 + 64 * 68) * 4)

// ---------- side stream ----------
static cudaStream_t g_sB;
static cudaEvent_t g_evFork, g_evJoin;
namespace {
struct StreamInit {
    StreamInit() {
        cudaStreamCreateWithFlags(&g_sB, cudaStreamNonBlocking);
        cudaEventCreateWithFlags(&g_evFork, cudaEventDisableTiming);
        cudaEventCreateWithFlags(&g_evJoin, cudaEventDisableTiming);
        cudaFuncSetAttribute(k_gemm8, cudaFuncAttributeMaxDynamicSharedMemorySize, SMEM8);
        cudaFuncSetAttribute(k_gemm1, cudaFuncAttributeMaxDynamicSharedMemorySize, SMEM1);
    }
};
StreamInit g_streamInit;
}

// ---------------------- prep: fp16 conversions ----------------------
__global__ __launch_bounds__(256) void k_x2h(const float* __restrict__ x, int total8) {
    int i = blockIdx.x * blockDim.x + threadIdx.x;
    if (i >= total8) return;
    float4 f0 = ((const float4*)x)[i * 2];
    float4 f1 = ((const float4*)x)[i * 2 + 1];
    __half2 h0 = __floats2half2_rn(f0.x, f0.y), h1 = __floats2half2_rn(f0.z, f0.w);
    __half2 h2 = __floats2half2_rn(f1.x, f1.y), h3 = __floats2half2_rn(f1.z, f1.w);
    uint4 u = {*(uint32_t*)&h0, *(uint32_t*)&h1, *(uint32_t*)&h2, *(uint32_t*)&h3};
    ((uint4*)g_x16)[i] = u;
}
template <int NC>
__global__ __launch_bounds__(256) void k_wcvt(const float* __restrict__ W, uint32_t* __restrict__ Wt) {
    int i = blockIdx.x * blockDim.x + threadIdx.x;
    if (i >= NC * 64) return;
    int col = i >> 6, kp = i & 63;
    __half2 h = __floats2half2_rn(W[(size_t)(2 * kp) * NC + col], W[(size_t)(2 * kp + 1) * NC + col]);
    Wt[col * 64 + kp] = *(uint32_t*)&h;
}

// ---------------------- CSR build ----------------------
__global__ void k_init_cnt(int n) {
    int i = blockIdx.x * blockDim.x + threadIdx.x;
    if (i < n) g_cnt[i] = 1;
}
__global__ void k_count(const int* __restrict__ dst, int e) {
    int i = blockIdx.x * blockDim.x + threadIdx.x;
    if (i < e) atomicAdd(&g_cnt[dst[i]], 1);
}
__global__ void k_scan1(int n) {
    __shared__ int sh[1024];
    int tid = threadIdx.x;
    int i = blockIdx.x * 1024 + tid;
    int v = (i < n) ? g_cnt[i] : 0;
    sh[tid] = v;
    __syncthreads();
    #pragma unroll
    for (int o = 1; o < 1024; o <<= 1) {
        int t = (tid >= o) ? sh[tid - o] : 0;
        __syncthreads();
        sh[tid] += t;
        __syncthreads();
    }
    if (i < n) g_rowptr[i] = sh[tid] - v;
    if (tid == 1023) g_part[blockIdx.x] = sh[1023];
}
__global__ void k_scan2(int nb) {
    __shared__ int sh[128];
    int tid = threadIdx.x;
    int v = (tid < nb) ? g_part[tid] : 0;
    sh[tid] = v;
    __syncthreads();
    #pragma unroll
    for (int o = 1; o < 128; o <<= 1) {
        int t = (tid >= o) ? sh[tid - o] : 0;
        __syncthreads();
        sh[tid] += t;
        __syncthreads();
    }
    if (tid < nb) g_part[tid] = sh[tid] - v;
}
__global__ void k_scan3(int n, int etot) {
    int i = blockIdx.x * 1024 + threadIdx.x;
    if (i < n) {
        int p = g_rowptr[i] + g_part[blockIdx.x];
        g_rowptr[i] = p;
        g_srcs[p] = i;
        g_dsts[p] = i;
        g_cnt[i] = p + 1;
    }
    if (i == 0) g_rowptr[n] = etot;
}
__global__ void k_scatter(const int* __restrict__ src, const int* __restrict__ dst, int e) {
    int i = blockIdx.x * blockDim.x + threadIdx.x;
    if (i < e) {
        int d = dst[i];
        int pos = atomicAdd(&g_cnt[d], 1);
        g_srcs[pos] = src[i];
        g_dsts[pos] = d;
    }
}

// ---------------------- edge weight precompute ----------------------
__global__ __launch_bounds__(256) void k_edgew8(const float* __restrict__ als,
                                                const float* __restrict__ ald,
                                                int etot) {
    int i = blockIdx.x * blockDim.x + threadIdx.x;
    if (i >= etot) return;
    int s = g_srcs[i], d = g_dsts[i];
    float4 a0 = *(const float4*)(als + (size_t)s * 8);
    float4 a1 = *(const float4*)(als + (size_t)s * 8 + 4);
    float4 b0 = *(const float4*)(ald + (size_t)d * 8);
    float4 b1 = *(const float4*)(ald + (size_t)d * 8 + 4);
    float x[8] = {a0.x + b0.x, a0.y + b0.y, a0.z + b0.z, a0.w + b0.w,
                  a1.x + b1.x, a1.y + b1.y, a1.z + b1.z, a1.w + b1.w};
    __half hw[8];
    #pragma unroll
    for (int h = 0; h < 8; h++) {
        float v = (x[h] > 0.f) ? x[h] : LRELU * x[h];
        hw[h] = __float2half_rn(__expf(v));
    }
    *(uint4*)(g_ew + (size_t)i * 8) = *(uint4*)hw;
}
__global__ __launch_bounds__(256) void k_edgew1(const float* __restrict__ als,
                                                const float* __restrict__ ald,
                                                int etot) {
    int i = blockIdx.x * blockDim.x + threadIdx.x;
    if (i >= etot) return;
    float x = als[g_srcs[i]] + ald[g_dsts[i]];
    x = (x > 0.f) ? x : LRELU * x;
    g_ew[i] = __float2half_rn(__expf(x));
}

// ---------------------- fp16 mma ----------------------
#define MMA_F16(d, a, b) \
    asm volatile("mma.sync.aligned.m16n8k16.row.col.f32.f16.f16.f32 " \
        "{%0,%1,%2,%3}, {%4,%5,%6,%7}, {%8,%9}, {%0,%1,%2,%3};" \
        : "+f"((d)[0]), "+f"((d)[1]), "+f"((d)[2]), "+f"((d)[3]) \
        : "r"((a)[0]), "r"((a)[1]), "r"((a)[2]), "r"((a)[3]), \
          "r"((b)[0]), "r"((b)[1]))

// ---------------------- GEMM 128x128 + attn coefs (8 heads x 16) ----------------------
__global__ __launch_bounds__(256) void k_gemm8(
    const __half* __restrict__ A, const uint32_t* __restrict__ Wt,
    const float* __restrict__ asr, const float* __restrict__ adr,
    __half* __restrict__ H, float* __restrict__ als, float* __restrict__ ald, int n)
{
    extern __shared__ uint32_t smem[];
    uint32_t* As32 = smem;             // [128][68]
    uint32_t* Bs32 = smem + 128 * 68;  // [128][68]
    int tid = threadIdx.x;
    int wid = tid >> 5, lane = tid & 31;
    int warp_m = wid >> 1, warp_n = wid & 1;
    int g = lane >> 2, c = lane & 3;
    int row0 = blockIdx.x * 128;

    #pragma unroll
    for (int l = 0; l < 8; l++) {
        int idx = tid + l * 256;       // 0..2047
        int r = idx >> 4, q = idx & 15;
        int gr = row0 + r;
        uint4 u = make_uint4(0, 0, 0, 0);
        if (gr < n) u = *(const uint4*)(A + (size_t)gr * 128 + q * 8);
        *(uint4*)&As32[r * 68 + q * 4] = u;
    }
    #pragma unroll
    for (int l = 0; l < 8; l++) {
        int idx = tid + l * 256;
        int col = idx >> 4, q = idx & 15;
        *(uint4*)&Bs32[col * 68 + q * 4] = *(const uint4*)(Wt + col * 64 + q * 4);
    }
    __syncthreads();

    float acc[2][8][4];
    #pragma unroll
    for (int mt = 0; mt < 2; mt++)
        #pragma unroll
        for (int nt = 0; nt < 8; nt++)
            #pragma unroll
            for (int j = 0; j < 4; j++) acc[mt][nt][j] = 0.f;

    #pragma unroll
    for (int ks = 0; ks < 8; ks++) {
        int kb = ks * 8;
        uint32_t bf[8][2];
        #pragma unroll
        for (int nt = 0; nt < 8; nt++) {
            int col = warp_n * 64 + nt * 8 + g;
            bf[nt][0] = Bs32[col * 68 + kb + c];
            bf[nt][1] = Bs32[col * 68 + kb + c + 4];
        }
        #pragma unroll
        for (int mt = 0; mt < 2; mt++) {
            int row = warp_m * 32 + mt * 16 + g;
            uint32_t af[4];
            af[0] = As32[row * 68 + kb + c];
            af[1] = As32[(row + 8) * 68 + kb + c];
            af[2] = As32[row * 68 + kb + c + 4];
            af[3] = As32[(row + 8) * 68 + kb + c + 4];
            #pragma unroll
            for (int nt = 0; nt < 8; nt++) MMA_F16(acc[mt][nt], af, bf[nt]);
        }
    }

    #pragma unroll
    for (int mt = 0; mt < 2; mt++) {
        int r_lo = row0 + warp_m * 32 + mt * 16 + g;
        int r_hi = r_lo + 8;
        float sA0[4] = {0, 0, 0, 0}, sA1[4] = {0, 0, 0, 0};
        float sD0[4] = {0, 0, 0, 0}, sD1[4] = {0, 0, 0, 0};
        #pragma unroll
        for (int nt = 0; nt < 8; nt++) {
            int col = warp_n * 64 + nt * 8 + c * 2;
            int hh = nt >> 1;
            float as0 = asr[col], as1 = asr[col + 1];
            float ad0 = adr[col], ad1 = adr[col + 1];
            float* d = acc[mt][nt];
            sA0[hh] = fmaf(d[0], as0, fmaf(d[1], as1, sA0[hh]));
            sA1[hh] = fmaf(d[2], as0, fmaf(d[3], as1, sA1[hh]));
            sD0[hh] = fmaf(d[0], ad0, fmaf(d[1], ad1, sD0[hh]));
            sD1[hh] = fmaf(d[2], ad0, fmaf(d[3], ad1, sD1[hh]));
            if (r_lo < n) *(__half2*)(H + (size_t)r_lo * 128 + col) = __floats2half2_rn(d[0], d[1]);
            if (r_hi < n) *(__half2*)(H + (size_t)r_hi * 128 + col) = __floats2half2_rn(d[2], d[3]);
        }
        #pragma unroll
        for (int hh = 0; hh < 4; hh++) {
            sA0[hh] += __shfl_xor_sync(0xFFFFFFFFu, sA0[hh], 1);
            sA0[hh] += __shfl_xor_sync(0xFFFFFFFFu, sA0[hh], 2);
            sA1[hh] += __shfl_xor_sync(0xFFFFFFFFu, sA1[hh], 1);
            sA1[hh] += __shfl_xor_sync(0xFFFFFFFFu, sA1[hh], 2);
            sD0[hh] += __shfl_xor_sync(0xFFFFFFFFu, sD0[hh], 1);
            sD0[hh] += __shfl_xor_sync(0xFFFFFFFFu, sD0[hh], 2);
            sD1[hh] += __shfl_xor_sync(0xFFFFFFFFu, sD1[hh], 1);
            sD1[hh] += __shfl_xor_sync(0xFFFFFFFFu, sD1[hh], 2);
        }
        if (c == 0) {
            #pragma unroll
            for (int hh = 0; hh < 4; hh++) {
                int hgl = warp_n * 4 + hh;
                if (r_lo < n) { als[(size_t)r_lo * 8 + hgl] = sA0[hh]; ald[(size_t)r_lo * 8 + hgl] = sD0[hh]; }
                if (r_hi < n) { als[(size_t)r_hi * 8 + hgl] = sA1[hh]; ald[(size_t)r_hi * 8 + hgl] = sD1[hh]; }
            }
        }
    }
}

// ---------------------- GEMM 128x64 + attn coefs (1 head x 64) ----------------------
__global__ __launch_bounds__(256) void k_gemm1(
    const __half* __restrict__ A, const uint32_t* __restrict__ Wt,
    const float* __restrict__ asr, const float* __restrict__ adr,
    __half* __restrict__ H, float* __restrict__ als, float* __restrict__ ald, int n)
{
    extern __shared__ uint32_t smem[];
    uint32_t* As32 = smem;             // [128][68]
    uint32_t* Bs32 = smem + 128 * 68;  // [64][68]
    int tid = threadIdx.x;
    int wid = tid >> 5, lane = tid & 31;
    int g = lane >> 2, c = lane & 3;
    int row0 = blockIdx.x * 128;

    #pragma unroll
    for (int l = 0; l < 8; l++) {
        int idx = tid + l * 256;
        int r = idx >> 4, q = idx & 15;
        int gr = row0 + r;
        uint4 u = make_uint4(0, 0, 0, 0);
        if (gr < n) u = *(const uint4*)(A + (size_t)gr * 128 + q * 8);
        *(uint4*)&As32[r * 68 + q * 4] = u;
    }
    #pragma unroll
    for (int l = 0; l < 4; l++) {
        int idx = tid + l * 256;       // 0..1023
        int col = idx >> 4, q = idx & 15;
        *(uint4*)&Bs32[col * 68 + q * 4] = *(const uint4*)(Wt + col * 64 + q * 4);
    }
    __syncthreads();

    float acc[8][4];
    #pragma unroll
    for (int nt = 0; nt < 8; nt++)
        #pragma unroll
        for (int j = 0; j < 4; j++) acc[nt][j] = 0.f;

    #pragma unroll
    for (int ks = 0; ks < 8; ks++) {
        int kb = ks * 8;
        int row = wid * 16 + g;
        uint32_t af[4];
        af[0] = As32[row * 68 + kb + c];
        af[1] = As32[(row + 8) * 68 + kb + c];
        af[2] = As32[row * 68 + kb + c + 4];
        af[3] = As32[(row + 8) * 68 + kb + c + 4];
        #pragma unroll
        for (int nt = 0; nt < 8; nt++) {
            int col = nt * 8 + g;
            uint32_t bf[2];
            bf[0] = Bs32[col * 68 + kb + c];
            bf[1] = Bs32[col * 68 + kb + c + 4];
            MMA_F16(acc[nt], af, bf);
        }
    }

    int r_lo = row0 + wid * 16 + g;
    int r_hi = r_lo + 8;
    float sA0 = 0.f, sA1 = 0.f, sD0 = 0.f, sD1 = 0.f;
    #pragma unroll
    for (int nt = 0; nt < 8; nt++) {
        int col = nt * 8 + c * 2;
        float as0 = asr[col], as1 = asr[col + 1];
        float ad0 = adr[col], ad1 = adr[col + 1];
        float* d = acc[nt];
        sA0 = fmaf(d[0], as0, fmaf(d[1], as1, sA0));
        sA1 = fmaf(d[2], as0, fmaf(d[3], as1, sA1));
        sD0 = fmaf(d[0], ad0, fmaf(d[1], ad1, sD0));
        sD1 = fmaf(d[2], ad0, fmaf(d[3], ad1, sD1));
        if (r_lo < n) *(__half2*)(H + (size_t)r_lo * 64 + col) = __floats2half2_rn(d[0], d[1]);
        if (r_hi < n) *(__half2*)(H + (size_t)r_hi * 64 + col) = __floats2half2_rn(d[2], d[3]);
    }
    sA0 += __shfl_xor_sync(0xFFFFFFFFu, sA0, 1); sA0 += __shfl_xor_sync(0xFFFFFFFFu, sA0, 2);
    sA1 += __shfl_xor_sync(0xFFFFFFFFu, sA1, 1); sA1 += __shfl_xor_sync(0xFFFFFFFFu, sA1, 2);
    sD0 += __shfl_xor_sync(0xFFFFFFFFu, sD0, 1); sD0 += __shfl_xor_sync(0xFFFFFFFFu, sD0, 2);
    sD1 += __shfl_xor_sync(0xFFFFFFFFu, sD1, 1); sD1 += __shfl_xor_sync(0xFFFFFFFFu, sD1, 2);
    if (c == 0) {
        if (r_lo < n) { als[r_lo] = sA0; ald[r_lo] = sD0; }
        if (r_hi < n) { als[r_hi] = sA1; ald[r_hi] = sD1; }
    }
}

// ---------------------- aggregation (8 heads x 16) + fused LN+ReLU ----------------------
__global__ __launch_bounds__(256) void k_agg8(
    const __half* __restrict__ H, const float* __restrict__ bias,
    const float* __restrict__ lng, const float* __restrict__ lnb,
    __half* __restrict__ out, int n)
{
    int w = (blockIdx.x * blockDim.x + threadIdx.x) >> 5;
    if (w >= n) return;
    int lane = threadIdx.x & 31;
    int s = g_rowptr[w], e2 = g_rowptr[w + 1];
    int hd = lane >> 2;
    int d0 = lane * 4;
    float denom = 0.f;
    float ax = 0.f, ay = 0.f, az = 0.f, aw = 0.f;

    int i = s;
    for (; i + 4 <= e2; i += 4) {
        int sv[4];
        float wv[4];
        #pragma unroll
        for (int j = 0; j < 4; j++) sv[j] = g_srcs[i + j];
        #pragma unroll
        for (int j = 0; j < 4; j++) wv[j] = __half2float(g_ew[(size_t)(i + j) * 8 + hd]);
        uint2 raw[4];
        #pragma unroll
        for (int j = 0; j < 4; j++) raw[j] = *(const uint2*)(H + (size_t)sv[j] * 128 + d0);
        #pragma unroll
        for (int j = 0; j < 4; j++) {
            denom += wv[j];
            float2 f01 = __half22float2(*(__half2*)&raw[j].x);
            float2 f23 = __half22float2(*(__half2*)&raw[j].y);
            ax = fmaf(wv[j], f01.x, ax); ay = fmaf(wv[j], f01.y, ay);
            az = fmaf(wv[j], f23.x, az); aw = fmaf(wv[j], f23.y, aw);
        }
    }
    for (; i < e2; ++i) {
        int s0 = g_srcs[i];
        float w0 = __half2float(g_ew[(size_t)i * 8 + hd]);
        denom += w0;
        uint2 raw = *(const uint2*)(H + (size_t)s0 * 128 + d0);
        float2 f01 = __half22float2(*(__half2*)&raw.x);
        float2 f23 = __half22float2(*(__half2*)&raw.y);
        ax = fmaf(w0, f01.x, ax); ay = fmaf(w0, f01.y, ay);
        az = fmaf(w0, f23.x, az); aw = fmaf(w0, f23.y, aw);
    }

    float inv = 1.f / denom;
    float4 bv = *(const float4*)(bias + d0);
    float ox = fmaf(ax, inv, bv.x);
    float oy = fmaf(ay, inv, bv.y);
    float oz = fmaf(az, inv, bv.z);
    float ow = fmaf(aw, inv, bv.w);

    float sm = ox + oy + oz + ow;
    #pragma unroll
    for (int o = 16; o; o >>= 1) sm += __shfl_xor_sync(0xFFFFFFFFu, sm, o);
    float mu = sm * (1.f / 128.f);
    float dx = ox - mu, dy = oy - mu, dz = oz - mu, dw = ow - mu;
    float q = dx * dx + dy * dy + dz * dz + dw * dw;
    #pragma unroll
    for (int o = 16; o; o >>= 1) q += __shfl_xor_sync(0xFFFFFFFFu, q, o);
    float rstd = rsqrtf(q * (1.f / 128.f) + 1e-5f);
    float4 gg = *(const float4*)(lng + d0);
    float4 bb = *(const float4*)(lnb + d0);
    ox = fmaxf(fmaf(dx * rstd, gg.x, bb.x), 0.f);
    oy = fmaxf(fmaf(dy * rstd, gg.y, bb.y), 0.f);
    oz = fmaxf(fmaf(dz * rstd, gg.z, bb.z), 0.f);
    ow = fmaxf(fmaf(dw * rstd, gg.w, bb.w), 0.f);

    __half2 h01 = __floats2half2_rn(ox, oy);
    __half2 h23 = __floats2half2_rn(oz, ow);
    uint2 packed = {*(uint32_t*)&h01, *(uint32_t*)&h23};
    *(uint2*)(out + (size_t)w * 128 + d0) = packed;
}

// ---------------------- aggregation (1 head x 64) + log_softmax ----------------------
__global__ __launch_bounds__(256) void k_agg1_lsm(
    const __half* __restrict__ H, const float* __restrict__ bias,
    float* __restrict__ out, int n)
{
    int w = (blockIdx.x * blockDim.x + threadIdx.x) >> 5;
    if (w >= n) return;
    int lane = threadIdx.x & 31;
    int s = g_rowptr[w], e2 = g_rowptr[w + 1];
    int d0 = lane * 2;

    float denom = 0.f, acc0 = 0.f, acc1 = 0.f;
    int i = s;
    for (; i + 4 <= e2; i += 4) {
        int sv[4];
        float wv[4];
        #pragma unroll
        for (int j = 0; j < 4; j++) sv[j] = g_srcs[i + j];
        #pragma unroll
        for (int j = 0; j < 4; j++) wv[j] = __half2float(g_ew[i + j]);
        __half2 hv[4];
        #pragma unroll
        for (int j = 0; j < 4; j++) hv[j] = *(const __half2*)(H + (size_t)sv[j] * 64 + d0);
        #pragma unroll
        for (int j = 0; j < 4; j++) {
            denom += wv[j];
            float2 f = __half22float2(hv[j]);
            acc0 = fmaf(wv[j], f.x, acc0);
            acc1 = fmaf(wv[j], f.y, acc1);
        }
    }
    for (; i < e2; ++i) {
        int s0 = g_srcs[i];
        float w0 = __half2float(g_ew[i]);
        denom += w0;
        float2 f = __half22float2(*(const __half2*)(H + (size_t)s0 * 64 + d0));
        acc0 = fmaf(w0, f.x, acc0); acc1 = fmaf(w0, f.y, acc1);
    }
    float inv = 1.f / denom;
    float v0 = fmaf(acc0, inv, bias[d0]);
    float v1 = fmaf(acc1, inv, bias[d0 + 1]);
    float mx = fmaxf(v0, v1);
    #pragma unroll
    for (int o = 16; o; o >>= 1) mx = fmaxf(mx, __shfl_xor_sync(0xFFFFFFFFu, mx, o));
    float se = __expf(v0 - mx) + __expf(v1 - mx);
    #pragma unroll
    for (int o = 16; o; o >>= 1) se += __shfl_xor_sync(0xFFFFFFFFu, se, o);
    float lse = mx + __logf(se);
    out[(size_t)w * 64 + d0] = v0 - lse;
    out[(size_t)w * 64 + d0 + 1] = v1 - lse;
}

// ---------------------- launcher ----------------------
extern "C" void kernel_launch(void* const* d_in, const int* in_sizes, int n_in,
                              void* d_out, int out_size) {
    const float* x   = (const float*)d_in[0];
    const int*   ei  = (const int*)d_in[1];
    const float* W0  = (const float*)d_in[2];
    const float* as0 = (const float*)d_in[3];
    const float* ad0 = (const float*)d_in[4];
    const float* b0  = (const float*)d_in[5];
    const float* W1  = (const float*)d_in[6];
    const float* as1 = (const float*)d_in[7];
    const float* ad1 = (const float*)d_in[8];
    const float* b1  = (const float*)d_in[9];
    const float* W2  = (const float*)d_in[10];
    const float* as2 = (const float*)d_in[11];
    const float* ad2 = (const float*)d_in[12];
    const float* b2  = (const float*)d_in[13];
    const float* ln1g = (const float*)d_in[14];
    const float* ln1b = (const float*)d_in[15];
    const float* ln2g = (const float*)d_in[16];
    const float* ln2b = (const float*)d_in[17];
    float* out = (float*)d_out;

    const int n = in_sizes[0] / 128;
    const int e = in_sizes[1] / 2;
    const int etot = e + n;
    const int* src = ei;
    const int* dst = ei + e;

    __half *h, *feat, *x16;
    float *als, *ald;
    uint32_t *w0t, *w1t, *w2t;
    cudaGetSymbolAddress((void**)&h, g_h);
    cudaGetSymbolAddress((void**)&feat, g_feat);
    cudaGetSymbolAddress((void**)&x16, g_x16);
    cudaGetSymbolAddress((void**)&als, g_als);
    cudaGetSymbolAddress((void**)&ald, g_ald);
    cudaGetSymbolAddress((void**)&w0t, g_w0t);
    cudaGetSymbolAddress((void**)&w1t, g_w1t);
    cudaGetSymbolAddress((void**)&w2t, g_w2t);

    const int nb_nodes256 = (n + 255) / 256;
    const int nb_edges256 = (e + 255) / 256;
    const int nb_etot256 = (etot + 255) / 256;
    const int nb_scan = (n + 1023) / 1024;
    const int nb_warp = (n * 32 + 255) / 256;
    const int nb_gemm = (n + 127) / 128;
    const int total8 = n * 128 / 8;

    // launch 1 on default stream, then LEGAL fork into stream B
    k_init_cnt<<<nb_nodes256, 256>>>(n);                             // launch 1
    cudaEventRecord(g_evFork, 0);
    cudaStreamWaitEvent(g_sB, g_evFork, 0);

    // stream B: fp16 prep + gemm0, overlapped with CSR build
    k_x2h<<<(total8 + 255) / 256, 256, 0, g_sB>>>(x, total8);        // launch 2
    k_wcvt<128><<<32, 256, 0, g_sB>>>(W0, w0t);                      // launch 3
    k_wcvt<128><<<32, 256, 0, g_sB>>>(W1, w1t);                      // launch 4
    k_wcvt<64><<<16, 256, 0, g_sB>>>(W2, w2t);                       // launch 5
    k_gemm8<<<nb_gemm, 256, SMEM8, g_sB>>>(x16, w0t, as0, ad0, h, als, ald, n);  // launch 6 (ncu)

    // default stream: rest of CSR build
    k_count<<<nb_edges256, 256>>>(dst, e);
    k_scan1<<<nb_scan, 1024>>>(n);
    k_scan2<<<1, 128>>>(nb_scan);
    k_scan3<<<nb_scan, 1024>>>(n, etot);
    k_scatter<<<nb_edges256, 256>>>(src, dst, e);

    cudaEventRecord(g_evJoin, g_sB);
    cudaStreamWaitEvent(0, g_evJoin, 0);

    k_edgew8<<<nb_etot256, 256>>>(als, ald, etot);
    k_agg8<<<nb_warp, 256>>>(h, b0, ln1g, ln1b, feat, n);

    k_gemm8<<<nb_gemm, 256, SMEM8>>>(feat, w1t, as1, ad1, h, als, ald, n);
    k_edgew8<<<nb_etot256, 256>>>(als, ald, etot);
    k_agg8<<<nb_warp, 256>>>(h, b1, ln2g, ln2b, feat, n);

    k_gemm1<<<nb_gemm, 256, SMEM1>>>(feat, w2t, as2, ad2, h, als, ald, n);
    k_edgew1<<<nb_etot256, 256>>>(als, ald, etot);
    k_agg1_lsm<<<nb_warp, 256>>>(h, b2, out, n);
}